// round 1
// baseline (speedup 1.0000x reference)
#include <cuda_runtime.h>
#include <math.h>

// ---------------- problem constants ----------------
#define Vv   30522
#define Hh   768
#define Ll   12
#define FFf  3072
#define NHh  12
#define DHh  64
#define Bb   32
#define Ss   128
#define NLl  10000
#define NTOK (Bb*Ss)          // 4096
#define EPS_LN  1e-12f
#define EPS_COS 1e-8f

// ---------------- device scratch (no allocations allowed) ----------------
__device__ float g_x  [NTOK*Hh];
__device__ float g_q  [NTOK*Hh];
__device__ float g_k  [NTOK*Hh];
__device__ float g_v  [NTOK*Hh];
__device__ float g_ctx[NTOK*Hh];
__device__ float g_y  [NTOK*Hh];
__device__ float g_h  [NTOK*FFf];
__device__ float g_bias[NTOK];
__device__ float g_cls[Bb*Hh];
__device__ float g_cn [Bb];
__device__ unsigned long long g_best[Bb];

// ---------------- helpers ----------------
__device__ __forceinline__ float blk_sum256(float v, volatile float* sred) {
    // 256 threads = 8 warps. sred must have >= 9 floats.
    int lane = threadIdx.x & 31, w = threadIdx.x >> 5;
    #pragma unroll
    for (int o = 16; o > 0; o >>= 1) v += __shfl_down_sync(0xffffffffu, v, o);
    if (lane == 0) sred[w] = v;
    __syncthreads();
    if (threadIdx.x == 0) {
        float s = 0.f;
        #pragma unroll
        for (int i = 0; i < 8; i++) s += sred[i];
        sred[8] = s;
    }
    __syncthreads();
    float r = sred[8];
    __syncthreads();  // protect scratch for next call
    return r;
}

__device__ __forceinline__ float gelu_tanh(float x) {
    float x3 = x * x * x;
    float t = tanhf(0.7978845608028654f * (x + 0.044715f * x3));
    return 0.5f * x * (1.0f + t);
}

__device__ __forceinline__ unsigned long long pack_key(float c, int l) {
    unsigned u = __float_as_uint(c);
    u = (u & 0x80000000u) ? ~u : (u | 0x80000000u);   // order-preserving map
    return ((unsigned long long)u << 32) | (unsigned long long)(0xFFFFFFFFu - (unsigned)l);
}

// ---------------- embeddings + LN + mask bias ----------------
__global__ void embed_ln_kernel(const int* __restrict__ ids, const int* __restrict__ tys,
                                const float* __restrict__ word, const float* __restrict__ pos,
                                const float* __restrict__ typ,
                                const float* __restrict__ eg, const float* __restrict__ eb) {
    __shared__ float sred[9];
    int t = blockIdx.x;              // token = b*S + s
    int s = t & (Ss - 1);
    int id = ids[t], ty = tys[t];
    float v[3];
    float loc = 0.f;
    #pragma unroll
    for (int i = 0; i < 3; i++) {
        int j = threadIdx.x + i * 256;
        v[i] = word[(size_t)id * Hh + j] + pos[(size_t)s * Hh + j] + typ[(size_t)ty * Hh + j];
        loc += v[i];
    }
    float mu = blk_sum256(loc, sred) * (1.0f / Hh);
    float l2 = 0.f;
    #pragma unroll
    for (int i = 0; i < 3; i++) { float d = v[i] - mu; l2 += d * d; }
    float var = blk_sum256(l2, sred) * (1.0f / Hh);
    float rstd = rsqrtf(var + EPS_LN);
    #pragma unroll
    for (int i = 0; i < 3; i++) {
        int j = threadIdx.x + i * 256;
        g_x[(size_t)t * Hh + j] = (v[i] - mu) * rstd * eg[j] + eb[j];
    }
    if (threadIdx.x == 0) g_bias[t] = (id > 0) ? 0.f : -10000.0f;
}

// ---------------- residual add + LN (in place on x) ----------------
__global__ void add_ln_kernel(float* __restrict__ x, const float* __restrict__ y,
                              const float* __restrict__ g, const float* __restrict__ b) {
    __shared__ float sred[9];
    size_t base = (size_t)blockIdx.x * Hh;
    float v[3];
    float loc = 0.f;
    #pragma unroll
    for (int i = 0; i < 3; i++) {
        int j = threadIdx.x + i * 256;
        v[i] = x[base + j] + y[base + j];
        loc += v[i];
    }
    float mu = blk_sum256(loc, sred) * (1.0f / Hh);
    float l2 = 0.f;
    #pragma unroll
    for (int i = 0; i < 3; i++) { float d = v[i] - mu; l2 += d * d; }
    float var = blk_sum256(l2, sred) * (1.0f / Hh);
    float rstd = rsqrtf(var + EPS_LN);
    #pragma unroll
    for (int i = 0; i < 3; i++) {
        int j = threadIdx.x + i * 256;
        x[base + j] = (v[i] - mu) * rstd * g[j] + b[j];
    }
}

// ---------------- SGEMM: C[M,N] = A[M,K] @ B[K,N] + bias, opt. GELU ----------------
// BM=BN=128, BK=8, 256 threads, 8x8 micro-tile. All dims multiples of tile sizes.
template <bool GELU>
__global__ void __launch_bounds__(256) gemm_bias(const float* __restrict__ A,
                                                 const float* __restrict__ B,
                                                 const float* __restrict__ bias,
                                                 float* __restrict__ C,
                                                 int M, int N, int K) {
    __shared__ float As[8][128];
    __shared__ float Bs[8][128];
    int tid = threadIdx.x;
    int row0 = blockIdx.y * 128, col0 = blockIdx.x * 128;
    int tr = tid >> 4, tc = tid & 15;               // 16x16 thread grid
    int arow = tid >> 1, acol4 = (tid & 1) * 4;     // A tile load map
    int brow = tid >> 5, bcol4 = (tid & 31) * 4;    // B tile load map
    const float* Aptr = A + (size_t)(row0 + arow) * K + acol4;
    const float* Bptr = B + (size_t)brow * N + col0 + bcol4;
    float acc[8][8];
    #pragma unroll
    for (int i = 0; i < 8; i++)
        #pragma unroll
        for (int j = 0; j < 8; j++) acc[i][j] = 0.f;

    for (int k0 = 0; k0 < K; k0 += 8) {
        float4 av = *(const float4*)(Aptr + k0);
        float4 bv = *(const float4*)(Bptr + (size_t)k0 * N);
        As[acol4 + 0][arow] = av.x;
        As[acol4 + 1][arow] = av.y;
        As[acol4 + 2][arow] = av.z;
        As[acol4 + 3][arow] = av.w;
        *(float4*)&Bs[brow][bcol4] = bv;
        __syncthreads();
        #pragma unroll
        for (int kk = 0; kk < 8; kk++) {
            float4 a0 = *(const float4*)&As[kk][tr * 8];
            float4 a1 = *(const float4*)&As[kk][tr * 8 + 4];
            float4 b0 = *(const float4*)&Bs[kk][tc * 8];
            float4 b1 = *(const float4*)&Bs[kk][tc * 8 + 4];
            float a[8] = {a0.x, a0.y, a0.z, a0.w, a1.x, a1.y, a1.z, a1.w};
            float bb[8] = {b0.x, b0.y, b0.z, b0.w, b1.x, b1.y, b1.z, b1.w};
            #pragma unroll
            for (int i = 0; i < 8; i++)
                #pragma unroll
                for (int j = 0; j < 8; j++) acc[i][j] = fmaf(a[i], bb[j], acc[i][j]);
        }
        __syncthreads();
    }
    // epilogue
    float bvl[8];
    #pragma unroll
    for (int j = 0; j < 8; j++) bvl[j] = bias[col0 + tc * 8 + j];
    #pragma unroll
    for (int i = 0; i < 8; i++) {
        float o[8];
        #pragma unroll
        for (int j = 0; j < 8; j++) {
            float c = acc[i][j] + bvl[j];
            o[j] = GELU ? gelu_tanh(c) : c;
        }
        float* cp = C + (size_t)(row0 + tr * 8 + i) * N + col0 + tc * 8;
        *(float4*)(cp)     = make_float4(o[0], o[1], o[2], o[3]);
        *(float4*)(cp + 4) = make_float4(o[4], o[5], o[6], o[7]);
    }
}

// ---------------- attention: one block per (b, head), K/V resident in smem ----------------
__global__ void __launch_bounds__(128) attn_kernel(const float* __restrict__ Q,
                                                   const float* __restrict__ K,
                                                   const float* __restrict__ V,
                                                   const float* __restrict__ bias,
                                                   float* __restrict__ ctx) {
    extern __shared__ float sm[];
    float* Ks = sm;                       // [128][64]
    float* Vs = sm + Ss * DHh;            // [128][64]
    float* biasS = sm + 2 * Ss * DHh;     // [128]
    int bn = blockIdx.x;
    int b = bn / NHh, n = bn % NHh;
    int tid = threadIdx.x;
    const float scale = 0.125f;           // 1/sqrt(64)

    // cooperative K/V load (float4, coalesced)
    #pragma unroll
    for (int i = 0; i < 16; i++) {
        int lin = tid + i * 128;          // 0..2047 float4's
        int j = lin >> 4, c4 = (lin & 15) * 4;
        size_t go = (size_t)(b * Ss + j) * Hh + n * DHh + c4;
        *(float4*)&Ks[j * DHh + c4] = *(const float4*)(K + go);
        *(float4*)&Vs[j * DHh + c4] = *(const float4*)(V + go);
    }
    biasS[tid] = bias[b * Ss + tid];
    __syncthreads();

    // one query row per thread
    int q = tid;
    float Qr[DHh];
    const float4* qp = (const float4*)(Q + (size_t)(b * Ss + q) * Hh + n * DHh);
    #pragma unroll
    for (int i = 0; i < 16; i++) {
        float4 v4 = qp[i];
        Qr[i * 4 + 0] = v4.x; Qr[i * 4 + 1] = v4.y; Qr[i * 4 + 2] = v4.z; Qr[i * 4 + 3] = v4.w;
    }

    // pass 1: online max + sumexp
    float m = -1e30f, lsum = 0.f;
    for (int j = 0; j < Ss; j++) {
        const float* kr = Ks + j * DHh;
        float s = 0.f;
        #pragma unroll
        for (int d = 0; d < DHh; d++) s = fmaf(Qr[d], kr[d], s);
        s = s * scale + biasS[j];
        float mn = fmaxf(m, s);
        lsum = lsum * __expf(m - mn) + __expf(s - mn);
        m = mn;
    }
    float inv_l = 1.0f / lsum;

    // pass 2: recompute p and accumulate V
    float acc[DHh];
    #pragma unroll
    for (int d = 0; d < DHh; d++) acc[d] = 0.f;
    for (int j = 0; j < Ss; j++) {
        const float* kr = Ks + j * DHh;
        float s = 0.f;
        #pragma unroll
        for (int d = 0; d < DHh; d++) s = fmaf(Qr[d], kr[d], s);
        s = s * scale + biasS[j];
        float p = __expf(s - m);
        const float* vr = Vs + j * DHh;
        #pragma unroll
        for (int d = 0; d < DHh; d++) acc[d] = fmaf(p, vr[d], acc[d]);
    }
    float4* cp = (float4*)(ctx + (size_t)(b * Ss + q) * Hh + n * DHh);
    #pragma unroll
    for (int i = 0; i < 16; i++)
        cp[i] = make_float4(acc[i * 4] * inv_l, acc[i * 4 + 1] * inv_l,
                            acc[i * 4 + 2] * inv_l, acc[i * 4 + 3] * inv_l);
}

// ---------------- CLS extraction + norm ----------------
__global__ void cls_kernel() {
    __shared__ float sred[9];
    int b = blockIdx.x;
    float loc = 0.f;
    #pragma unroll
    for (int i = 0; i < 3; i++) {
        int j = threadIdx.x + i * 256;
        float v = g_x[(size_t)(b * Ss) * Hh + j];
        g_cls[b * Hh + j] = v;
        loc += v * v;
    }
    float s = blk_sum256(loc, sred);
    if (threadIdx.x == 0) g_cn[b] = fmaxf(sqrtf(s), EPS_COS);
}

__global__ void reset_best_kernel() {
    if (threadIdx.x < Bb) g_best[threadIdx.x] = 0ull;
}

// ---------------- cosine + per-block argmax reduction ----------------
__global__ void __launch_bounds__(128) cos_kernel(const float* __restrict__ lab,
                                                  float* __restrict__ out) {
    __shared__ float clsS[Bb][33];
    __shared__ float sInvCn[Bb];
    int l = blockIdx.x * 128 + threadIdx.x;
    bool valid = (l < NLl);
    if (threadIdx.x < Bb) sInvCn[threadIdx.x] = 1.0f / g_cn[threadIdx.x];

    float acc[Bb];
    #pragma unroll
    for (int bb = 0; bb < Bb; bb++) acc[bb] = 0.f;

    for (int k0 = 0; k0 < Hh; k0 += 32) {
        #pragma unroll
        for (int i = 0; i < 8; i++) {
            int idx = threadIdx.x + i * 128;
            int bb = idx >> 5, kk = idx & 31;
            clsS[bb][kk] = g_cls[bb * Hh + k0 + kk];
        }
        __syncthreads();
        if (valid) {
            float lv[32];
            const float4* lp = (const float4*)(lab + (size_t)l * Hh + k0);
            #pragma unroll
            for (int i = 0; i < 8; i++) {
                float4 v4 = lp[i];
                lv[i * 4] = v4.x; lv[i * 4 + 1] = v4.y; lv[i * 4 + 2] = v4.z; lv[i * 4 + 3] = v4.w;
            }
            #pragma unroll
            for (int bb = 0; bb < Bb; bb++) {
                float a = acc[bb];
                #pragma unroll
                for (int kk = 0; kk < 32; kk++) a = fmaf(clsS[bb][kk], lv[kk], a);
                acc[bb] = a;
            }
        }
        __syncthreads();
    }

    // label norm (exact from the same lv sweep would need storage; recompute cheaply)
    float invl = 0.f;
    if (valid) {
        float s = 0.f;
        const float4* lp = (const float4*)(lab + (size_t)l * Hh);
        #pragma unroll 4
        for (int i = 0; i < Hh / 4; i++) {
            float4 v4 = lp[i];
            s += v4.x * v4.x + v4.y * v4.y + v4.z * v4.z + v4.w * v4.w;
        }
        invl = 1.0f / fmaxf(sqrtf(s), EPS_COS);
    }

    int lane = threadIdx.x & 31;
    #pragma unroll 1
    for (int bb = 0; bb < Bb; bb++) {
        unsigned long long key = 0ull;
        if (valid) {
            float c = acc[bb] * invl * sInvCn[bb];
            out[(size_t)bb * NLl + l] = c;
            key = pack_key(c, l);
        }
        #pragma unroll
        for (int o = 16; o > 0; o >>= 1) {
            unsigned long long other = __shfl_down_sync(0xffffffffu, key, o);
            key = (other > key) ? other : key;
        }
        if (lane == 0) atomicMax(&g_best[bb], key);
    }
}

__global__ void ids_out_kernel(float* __restrict__ out) {
    int b = threadIdx.x;
    if (b < Bb) {
        unsigned idpart = (unsigned)(g_best[b] & 0xFFFFFFFFull);
        out[(size_t)Bb * NLl + b] = (float)(0xFFFFFFFFu - idpart);
    }
}

// ---------------- host orchestration ----------------
extern "C" void kernel_launch(void* const* d_in, const int* in_sizes, int n_in,
                              void* d_out, int out_size) {
    const int*   ids  = (const int*)d_in[0];
    const int*   tys  = (const int*)d_in[1];
    const float* word = (const float*)d_in[2];
    const float* pos  = (const float*)d_in[3];
    const float* typ  = (const float*)d_in[4];
    const float* eg   = (const float*)d_in[5];
    const float* eb   = (const float*)d_in[6];
    const float* Wq   = (const float*)d_in[7];
    const float* bq   = (const float*)d_in[8];
    const float* Wk   = (const float*)d_in[9];
    const float* bk   = (const float*)d_in[10];
    const float* Wv   = (const float*)d_in[11];
    const float* bv   = (const float*)d_in[12];
    const float* Wo   = (const float*)d_in[13];
    const float* bo   = (const float*)d_in[14];
    const float* g1   = (const float*)d_in[15];
    const float* be1  = (const float*)d_in[16];
    const float* W1   = (const float*)d_in[17];
    const float* b1   = (const float*)d_in[18];
    const float* W2   = (const float*)d_in[19];
    const float* b2   = (const float*)d_in[20];
    const float* g2   = (const float*)d_in[21];
    const float* be2  = (const float*)d_in[22];
    const float* lab  = (const float*)d_in[23];
    float* out = (float*)d_out;

    float *px, *pq, *pk, *pv, *pctx, *py, *ph, *pbias;
    cudaGetSymbolAddress((void**)&px,    g_x);
    cudaGetSymbolAddress((void**)&pq,    g_q);
    cudaGetSymbolAddress((void**)&pk,    g_k);
    cudaGetSymbolAddress((void**)&pv,    g_v);
    cudaGetSymbolAddress((void**)&pctx,  g_ctx);
    cudaGetSymbolAddress((void**)&py,    g_y);
    cudaGetSymbolAddress((void**)&ph,    g_h);
    cudaGetSymbolAddress((void**)&pbias, g_bias);

    const int attn_smem = (2 * Ss * DHh + Ss) * (int)sizeof(float);  // 66048 B
    cudaFuncSetAttribute(attn_kernel, cudaFuncAttributeMaxDynamicSharedMemorySize, attn_smem);

    embed_ln_kernel<<<NTOK, 256>>>(ids, tys, word, pos, typ, eg, eb);

    for (int l = 0; l < Ll; l++) {
        size_t whh = (size_t)l * Hh * Hh;
        size_t wh  = (size_t)l * Hh;
        size_t wf1 = (size_t)l * Hh * FFf;
        size_t wf  = (size_t)l * FFf;
        gemm_bias<false><<<dim3(6, 32), 256>>>(px,  Wq + whh, bq + wh, pq, NTOK, Hh, Hh);
        gemm_bias<false><<<dim3(6, 32), 256>>>(px,  Wk + whh, bk + wh, pk, NTOK, Hh, Hh);
        gemm_bias<false><<<dim3(6, 32), 256>>>(px,  Wv + whh, bv + wh, pv, NTOK, Hh, Hh);
        attn_kernel<<<Bb * NHh, 128, attn_smem>>>(pq, pk, pv, pbias, pctx);
        gemm_bias<false><<<dim3(6, 32), 256>>>(pctx, Wo + whh, bo + wh, py, NTOK, Hh, Hh);
        add_ln_kernel<<<NTOK, 256>>>(px, py, g1 + wh, be1 + wh);
        gemm_bias<true ><<<dim3(24, 32), 256>>>(px, W1 + wf1, b1 + wf, ph, NTOK, FFf, Hh);
        gemm_bias<false><<<dim3(6, 32), 256>>>(ph, W2 + wf1, b2 + wh, py, NTOK, Hh, FFf);
        add_ln_kernel<<<NTOK, 256>>>(px, py, g2 + wh, be2 + wh);
    }

    cls_kernel<<<Bb, 256>>>();
    reset_best_kernel<<<1, 32>>>();
    cos_kernel<<<(NLl + 127) / 128, 128>>>(lab, out);
    if (out_size >= Bb * NLl + Bb) ids_out_kernel<<<1, 32>>>(out);
}

// round 3
// speedup vs baseline: 2.0952x; 2.0952x over previous
#include <cuda_runtime.h>
#include <cuda_bf16.h>
#include <math.h>
#include <cstdint>

// ---------------- problem constants ----------------
#define Vv   30522
#define Hh   768
#define Ll   12
#define FFf  3072
#define NHh  12
#define DHh  64
#define Bb   32
#define Ss   128
#define NLl  10000
#define NTOK (Bb*Ss)          // 4096
#define QKVN (3*Hh)           // 2304
#define EPS_LN  1e-12f
#define EPS_COS 1e-8f

// transposed split-weight layout per layer (element offsets)
#define OFF_O   (QKVN*Hh)             // after packed qkv [2304][768]
#define OFF_W1  (OFF_O + Hh*Hh)       // [3072][768]
#define OFF_W2  (OFF_W1 + Hh*FFf)     // [768][3072]
#define LSTRIDE (OFF_W2 + FFf*Hh)     // 7,077,888

// ---------------- device scratch ----------------
__device__ __nv_bfloat16 g_wthi[Ll*LSTRIDE];
__device__ __nv_bfloat16 g_wtlo[Ll*LSTRIDE];
__device__ float g_bqkv[Ll*QKVN];

__device__ float         g_x  [NTOK*Hh];
__device__ __nv_bfloat16 g_xhi[NTOK*Hh];
__device__ __nv_bfloat16 g_xlo[NTOK*Hh];
__device__ float         g_qkv[NTOK*QKVN];
__device__ __nv_bfloat16 g_chi[NTOK*Hh];
__device__ __nv_bfloat16 g_clo[NTOK*Hh];
__device__ __nv_bfloat16 g_hhi[NTOK*FFf];
__device__ __nv_bfloat16 g_hlo[NTOK*FFf];
__device__ float         g_y  [NTOK*Hh];
__device__ float g_mbias[NTOK];
__device__ float g_cls[Bb*Hh];
__device__ float g_cn [Bb];
__device__ unsigned long long g_best[Bb];

// ---------------- PTX helpers (compute_100-safe: mma.sync / ldmatrix / cp.async) ----------------
__device__ __forceinline__ uint32_t smem_u32(const void* p) {
    uint32_t a;
    asm("{ .reg .u64 t; cvta.to.shared.u64 t, %1; cvt.u32.u64 %0, t; }" : "=r"(a) : "l"(p));
    return a;
}
__device__ __forceinline__ void cp_async16(uint32_t dst, const void* src) {
    asm volatile("cp.async.cg.shared.global [%0], [%1], 16;" :: "r"(dst), "l"(src) : "memory");
}
#define CP_COMMIT() asm volatile("cp.async.commit_group;" ::: "memory")
#define CP_WAIT(n)  asm volatile("cp.async.wait_group %0;" :: "n"(n) : "memory")

__device__ __forceinline__ void ldsm4(uint32_t& r0, uint32_t& r1, uint32_t& r2, uint32_t& r3,
                                      uint32_t addr) {
    asm volatile("ldmatrix.sync.aligned.m8n8.x4.shared.b16 {%0,%1,%2,%3}, [%4];"
                 : "=r"(r0), "=r"(r1), "=r"(r2), "=r"(r3) : "r"(addr));
}
__device__ __forceinline__ void mma16816(float* c, uint32_t a0, uint32_t a1, uint32_t a2,
                                         uint32_t a3, uint32_t b0, uint32_t b1) {
    asm volatile(
        "mma.sync.aligned.m16n8k16.row.col.f32.bf16.bf16.f32 "
        "{%0,%1,%2,%3}, {%4,%5,%6,%7}, {%8,%9}, {%0,%1,%2,%3};"
        : "+f"(c[0]), "+f"(c[1]), "+f"(c[2]), "+f"(c[3])
        : "r"(a0), "r"(a1), "r"(a2), "r"(a3), "r"(b0), "r"(b1));
}

// ---------------- misc helpers ----------------
__device__ __forceinline__ float blk_sum256(float v, volatile float* sred) {
    int lane = threadIdx.x & 31, w = threadIdx.x >> 5;
    #pragma unroll
    for (int o = 16; o > 0; o >>= 1) v += __shfl_down_sync(0xffffffffu, v, o);
    if (lane == 0) sred[w] = v;
    __syncthreads();
    if (threadIdx.x == 0) {
        float s = 0.f;
        #pragma unroll
        for (int i = 0; i < 8; i++) s += sred[i];
        sred[8] = s;
    }
    __syncthreads();
    float r = sred[8];
    __syncthreads();
    return r;
}
__device__ __forceinline__ float gelu_tanh(float x) {
    float x3 = x * x * x;
    float t = tanhf(0.7978845608028654f * (x + 0.044715f * x3));
    return 0.5f * x * (1.0f + t);
}
__device__ __forceinline__ unsigned long long pack_key(float c, int l) {
    unsigned u = __float_as_uint(c);
    u = (u & 0x80000000u) ? ~u : (u | 0x80000000u);
    return ((unsigned long long)u << 32) | (unsigned long long)(0xFFFFFFFFu - (unsigned)l);
}
__device__ __forceinline__ void split_store(float v, __nv_bfloat16* hi, __nv_bfloat16* lo) {
    __nv_bfloat16 h = __float2bfloat16(v);
    *hi = h;
    *lo = __float2bfloat16(v - __bfloat162float(h));
}

// ---------------- weight transpose + bf16 split ----------------
__global__ void wsplit_kernel(const float* __restrict__ W, long dstOff, int K, int N) {
    __shared__ float t[32][33];
    int l = blockIdx.z;
    const float* Ws = W + (size_t)l * K * N;
    __nv_bfloat16* th = g_wthi + (size_t)l * LSTRIDE + dstOff;
    __nv_bfloat16* tl = g_wtlo + (size_t)l * LSTRIDE + dstOff;
    int n = blockIdx.x * 32 + threadIdx.x;
    #pragma unroll
    for (int i = 0; i < 4; i++) {
        int k = blockIdx.y * 32 + threadIdx.y + i * 8;
        t[threadIdx.y + i * 8][threadIdx.x] = Ws[(size_t)k * N + n];
    }
    __syncthreads();
    int k2 = blockIdx.y * 32 + threadIdx.x;
    #pragma unroll
    for (int i = 0; i < 4; i++) {
        int n2 = blockIdx.x * 32 + threadIdx.y + i * 8;
        float v = t[threadIdx.x][threadIdx.y + i * 8];
        split_store(v, &th[(size_t)n2 * K + k2], &tl[(size_t)n2 * K + k2]);
    }
}

__global__ void pack_bias_kernel(const float* __restrict__ bq, const float* __restrict__ bk,
                                 const float* __restrict__ bv) {
    int l = blockIdx.x, j = threadIdx.x;
    g_bqkv[l * QKVN + j]          = bq[l * Hh + j];
    g_bqkv[l * QKVN + Hh + j]     = bk[l * Hh + j];
    g_bqkv[l * QKVN + 2 * Hh + j] = bv[l * Hh + j];
}

// ---------------- embeddings + LN + mask bias ----------------
__global__ void embed_ln_kernel(const int* __restrict__ ids, const int* __restrict__ tys,
                                const float* __restrict__ word, const float* __restrict__ pos,
                                const float* __restrict__ typ,
                                const float* __restrict__ eg, const float* __restrict__ eb) {
    __shared__ float sred[9];
    int t = blockIdx.x;
    int s = t & (Ss - 1);
    int id = ids[t], ty = tys[t];
    float v[3];
    float loc = 0.f;
    #pragma unroll
    for (int i = 0; i < 3; i++) {
        int j = threadIdx.x + i * 256;
        v[i] = word[(size_t)id * Hh + j] + pos[(size_t)s * Hh + j] + typ[(size_t)ty * Hh + j];
        loc += v[i];
    }
    float mu = blk_sum256(loc, sred) * (1.0f / Hh);
    float l2 = 0.f;
    #pragma unroll
    for (int i = 0; i < 3; i++) { float d = v[i] - mu; l2 += d * d; }
    float var = blk_sum256(l2, sred) * (1.0f / Hh);
    float rstd = rsqrtf(var + EPS_LN);
    #pragma unroll
    for (int i = 0; i < 3; i++) {
        int j = threadIdx.x + i * 256;
        size_t idx = (size_t)t * Hh + j;
        float o = (v[i] - mu) * rstd * eg[j] + eb[j];
        g_x[idx] = o;
        split_store(o, &g_xhi[idx], &g_xlo[idx]);
    }
    if (threadIdx.x == 0) g_mbias[t] = (id > 0) ? 0.f : -10000.0f;
}

// ---------------- residual add + LN (in place on x), fused bf16 split ----------------
__global__ void add_ln_kernel(float* __restrict__ x, const float* __restrict__ y,
                              const float* __restrict__ g, const float* __restrict__ b) {
    __shared__ float sred[9];
    size_t base = (size_t)blockIdx.x * Hh;
    float v[3];
    float loc = 0.f;
    #pragma unroll
    for (int i = 0; i < 3; i++) {
        int j = threadIdx.x + i * 256;
        v[i] = x[base + j] + y[base + j];
        loc += v[i];
    }
    float mu = blk_sum256(loc, sred) * (1.0f / Hh);
    float l2 = 0.f;
    #pragma unroll
    for (int i = 0; i < 3; i++) { float d = v[i] - mu; l2 += d * d; }
    float var = blk_sum256(l2, sred) * (1.0f / Hh);
    float rstd = rsqrtf(var + EPS_LN);
    #pragma unroll
    for (int i = 0; i < 3; i++) {
        int j = threadIdx.x + i * 256;
        float o = (v[i] - mu) * rstd * g[j] + b[j];
        x[base + j] = o;
        split_store(o, &g_xhi[base + j], &g_xlo[base + j]);
    }
}

// ---------------- HMMA split-bf16 GEMM: C[4096, N] = A @ W^T + bias ----------------
// A: hi/lo bf16 [M][K]; B: transposed hi/lo bf16 [N][K].
// CTA: 128x128 tile, K-chunk 32, double-buffered cp.async, 8 warps (warp tile 64x32).
// 3 Markidis terms: AhBh + AlBh + AhBl (fp32 accum).
// smem tile layout: [stage][Ah|Al|Bh|Bl], rows padded to 40 bf16 (80B) for ldmatrix.
#define GT_TILE  (128 * 80)        // bytes per sub-tile
#define GT_STAGE (4 * GT_TILE)     // 40960
#define GSMEM    (2 * GT_STAGE)    // 81920
template <int OUTMODE>
__global__ void __launch_bounds__(256) gemm_mma(
    const __nv_bfloat16* __restrict__ Ahi, const __nv_bfloat16* __restrict__ Alo,
    const __nv_bfloat16* __restrict__ Bhi, const __nv_bfloat16* __restrict__ Blo,
    const float* __restrict__ bias,
    float* __restrict__ Cf, __nv_bfloat16* __restrict__ Chi, __nv_bfloat16* __restrict__ Clo,
    int K, int ldc)
{
    extern __shared__ char sm[];
    const uint32_t sb = smem_u32(sm);
    int tid = threadIdx.x, lane = tid & 31, wid = tid >> 5;
    int wm = wid >> 2, wn = wid & 3;              // warp tile: rows wm*64, cols wn*32
    int m0 = blockIdx.y * 128, n0 = blockIdx.x * 128;

    // ldmatrix lane offsets
    int q = lane >> 3, r = lane & 7;
    uint32_t aLane = (uint32_t)(((q & 1) * 8 + r) * 80 + (q >> 1) * 16);
    uint32_t bLane = (uint32_t)(((q >> 1) * 8 + r) * 80 + (q & 1) * 16);

    float acc[4][4][4];
    #pragma unroll
    for (int mi = 0; mi < 4; mi++)
        #pragma unroll
        for (int ni = 0; ni < 4; ni++)
            #pragma unroll
            for (int e = 0; e < 4; e++) acc[mi][ni][e] = 0.f;

    // per-thread load mapping: 8 cp.async of 16B (4 for A-halves, 4 for B-halves)
    int l_hl  = tid >> 7;                 // 0..1 (hi/lo)
    int l_row = (tid >> 1) & 63;          // row base (two rows per thread via i)
    int l_seg = tid & 1;                  // two segs per thread via i

    int nchunk = K >> 5;

    auto load_stage = [&](int c) {
        int k0 = c << 5;
        uint32_t base = sb + (uint32_t)(c & 1) * GT_STAGE;
        #pragma unroll
        for (int i = 0; i < 2; i++) {
            int row = l_row + i * 64;
            #pragma unroll
            for (int j = 0; j < 2; j++) {
                int seg = l_seg + j * 2;
                uint32_t off = (uint32_t)(row * 80 + seg * 16);
                const __nv_bfloat16* asrc =
                    (l_hl ? Alo : Ahi) + (size_t)(m0 + row) * K + k0 + seg * 8;
                const __nv_bfloat16* bsrc =
                    (l_hl ? Blo : Bhi) + (size_t)(n0 + row) * K + k0 + seg * 8;
                cp_async16(base + (uint32_t)l_hl * GT_TILE + off, asrc);
                cp_async16(base + (uint32_t)(2 + l_hl) * GT_TILE + off, bsrc);
            }
        }
    };

    load_stage(0);
    CP_COMMIT();

    for (int c = 0; c < nchunk; c++) {
        if (c + 1 < nchunk) { load_stage(c + 1); CP_COMMIT(); CP_WAIT(1); }
        else { CP_WAIT(0); }
        __syncthreads();

        uint32_t base = sb + (uint32_t)(c & 1) * GT_STAGE;
        uint32_t aBaseH = base + (uint32_t)((wm * 64) * 80) + aLane;
        uint32_t aBaseL = aBaseH + GT_TILE;
        uint32_t bBaseH = base + 2 * GT_TILE + (uint32_t)((wn * 32) * 80) + bLane;
        uint32_t bBaseL = bBaseH + GT_TILE;

        #pragma unroll
        for (int ks = 0; ks < 2; ks++) {
            uint32_t ko = (uint32_t)(ks * 32);
            uint32_t ah[4][4], al[4][4], bf[2][4];
            #pragma unroll
            for (int mi = 0; mi < 4; mi++)
                ldsm4(ah[mi][0], ah[mi][1], ah[mi][2], ah[mi][3],
                      aBaseH + (uint32_t)(mi * 16 * 80) + ko);
            #pragma unroll
            for (int mi = 0; mi < 4; mi++)
                ldsm4(al[mi][0], al[mi][1], al[mi][2], al[mi][3],
                      aBaseL + (uint32_t)(mi * 16 * 80) + ko);
            #pragma unroll
            for (int p = 0; p < 2; p++)
                ldsm4(bf[p][0], bf[p][1], bf[p][2], bf[p][3],
                      bBaseH + (uint32_t)(p * 16 * 80) + ko);
            // Ah*Bh + Al*Bh
            #pragma unroll
            for (int mi = 0; mi < 4; mi++)
                #pragma unroll
                for (int ni = 0; ni < 4; ni++) {
                    int p = ni >> 1, su = ni & 1;
                    mma16816(acc[mi][ni], ah[mi][0], ah[mi][1], ah[mi][2], ah[mi][3],
                             bf[p][su * 2], bf[p][su * 2 + 1]);
                }
            #pragma unroll
            for (int mi = 0; mi < 4; mi++)
                #pragma unroll
                for (int ni = 0; ni < 4; ni++) {
                    int p = ni >> 1, su = ni & 1;
                    mma16816(acc[mi][ni], al[mi][0], al[mi][1], al[mi][2], al[mi][3],
                             bf[p][su * 2], bf[p][su * 2 + 1]);
                }
            // reload B as lo, Ah*Bl
            #pragma unroll
            for (int p = 0; p < 2; p++)
                ldsm4(bf[p][0], bf[p][1], bf[p][2], bf[p][3],
                      bBaseL + (uint32_t)(p * 16 * 80) + ko);
            #pragma unroll
            for (int mi = 0; mi < 4; mi++)
                #pragma unroll
                for (int ni = 0; ni < 4; ni++) {
                    int p = ni >> 1, su = ni & 1;
                    mma16816(acc[mi][ni], ah[mi][0], ah[mi][1], ah[mi][2], ah[mi][3],
                             bf[p][su * 2], bf[p][su * 2 + 1]);
                }
        }
        __syncthreads();
    }

    // ---------------- epilogue ----------------
    int rbase = m0 + wm * 64 + (lane >> 2);
    int cbase = n0 + wn * 32 + (lane & 3) * 2;
    #pragma unroll
    for (int mi = 0; mi < 4; mi++) {
        #pragma unroll
        for (int ni = 0; ni < 4; ni++) {
            int row = rbase + mi * 16;
            int col = cbase + ni * 8;
            float b0 = bias[col], b1 = bias[col + 1];
            float v0 = acc[mi][ni][0] + b0, v1 = acc[mi][ni][1] + b1;
            float v2 = acc[mi][ni][2] + b0, v3 = acc[mi][ni][3] + b1;
            if (OUTMODE == 0) {
                *(float2*)(Cf + (size_t)row * ldc + col)       = make_float2(v0, v1);
                *(float2*)(Cf + (size_t)(row + 8) * ldc + col) = make_float2(v2, v3);
            } else {
                v0 = gelu_tanh(v0); v1 = gelu_tanh(v1);
                v2 = gelu_tanh(v2); v3 = gelu_tanh(v3);
                __nv_bfloat16 h0 = __float2bfloat16(v0), h1 = __float2bfloat16(v1);
                __nv_bfloat16 h2 = __float2bfloat16(v2), h3 = __float2bfloat16(v3);
                __nv_bfloat16 l0 = __float2bfloat16(v0 - __bfloat162float(h0));
                __nv_bfloat16 l1 = __float2bfloat16(v1 - __bfloat162float(h1));
                __nv_bfloat16 l2 = __float2bfloat16(v2 - __bfloat162float(h2));
                __nv_bfloat16 l3 = __float2bfloat16(v3 - __bfloat162float(h3));
                *(unsigned*)(Chi + (size_t)row * ldc + col) =
                    (unsigned)__bfloat16_as_ushort(h0) | ((unsigned)__bfloat16_as_ushort(h1) << 16);
                *(unsigned*)(Clo + (size_t)row * ldc + col) =
                    (unsigned)__bfloat16_as_ushort(l0) | ((unsigned)__bfloat16_as_ushort(l1) << 16);
                *(unsigned*)(Chi + (size_t)(row + 8) * ldc + col) =
                    (unsigned)__bfloat16_as_ushort(h2) | ((unsigned)__bfloat16_as_ushort(h3) << 16);
                *(unsigned*)(Clo + (size_t)(row + 8) * ldc + col) =
                    (unsigned)__bfloat16_as_ushort(l2) | ((unsigned)__bfloat16_as_ushort(l3) << 16);
            }
        }
    }
}

// ---------------- attention: packed qkv in, bf16 hi/lo ctx out ----------------
__global__ void __launch_bounds__(128) attn_kernel(const float* __restrict__ Qkv,
                                                   const float* __restrict__ bias,
                                                   __nv_bfloat16* __restrict__ chi,
                                                   __nv_bfloat16* __restrict__ clo) {
    extern __shared__ float smf[];
    float* Ks = smf;
    float* Vs = smf + Ss * DHh;
    float* biasS = smf + 2 * Ss * DHh;
    int bn = blockIdx.x;
    int b = bn / NHh, n = bn % NHh;
    int tid = threadIdx.x;
    const float scale = 0.125f;

    #pragma unroll
    for (int i = 0; i < 16; i++) {
        int linr = tid + i * 128;
        int j = linr >> 4, c4 = (linr & 15) * 4;
        size_t rowb = (size_t)(b * Ss + j) * QKVN + n * DHh + c4;
        *(float4*)&Ks[j * DHh + c4] = *(const float4*)(Qkv + rowb + Hh);
        *(float4*)&Vs[j * DHh + c4] = *(const float4*)(Qkv + rowb + 2 * Hh);
    }
    biasS[tid] = bias[b * Ss + tid];
    __syncthreads();

    int qi = tid;
    float Qr[DHh];
    const float4* qp = (const float4*)(Qkv + (size_t)(b * Ss + qi) * QKVN + n * DHh);
    #pragma unroll
    for (int i = 0; i < 16; i++) {
        float4 v4 = qp[i];
        Qr[i * 4 + 0] = v4.x; Qr[i * 4 + 1] = v4.y; Qr[i * 4 + 2] = v4.z; Qr[i * 4 + 3] = v4.w;
    }

    float m = -1e30f, lsum = 0.f;
    for (int j = 0; j < Ss; j++) {
        const float* kr = Ks + j * DHh;
        float s = 0.f;
        #pragma unroll
        for (int d = 0; d < DHh; d++) s = fmaf(Qr[d], kr[d], s);
        s = s * scale + biasS[j];
        float mn = fmaxf(m, s);
        lsum = lsum * __expf(m - mn) + __expf(s - mn);
        m = mn;
    }
    float inv_l = 1.0f / lsum;

    float acc[DHh];
    #pragma unroll
    for (int d = 0; d < DHh; d++) acc[d] = 0.f;
    for (int j = 0; j < Ss; j++) {
        const float* kr = Ks + j * DHh;
        float s = 0.f;
        #pragma unroll
        for (int d = 0; d < DHh; d++) s = fmaf(Qr[d], kr[d], s);
        s = s * scale + biasS[j];
        float p = __expf(s - m);
        const float* vr = Vs + j * DHh;
        #pragma unroll
        for (int d = 0; d < DHh; d++) acc[d] = fmaf(p, vr[d], acc[d]);
    }
    size_t obase = (size_t)(b * Ss + qi) * Hh + n * DHh;
    #pragma unroll
    for (int d = 0; d < DHh; d += 2) {
        float v0 = acc[d] * inv_l, v1 = acc[d + 1] * inv_l;
        __nv_bfloat16 h0 = __float2bfloat16(v0);
        __nv_bfloat16 h1 = __float2bfloat16(v1);
        __nv_bfloat16 l0 = __float2bfloat16(v0 - __bfloat162float(h0));
        __nv_bfloat16 l1 = __float2bfloat16(v1 - __bfloat162float(h1));
        *(unsigned*)(chi + obase + d) =
            (unsigned)__bfloat16_as_ushort(h0) | ((unsigned)__bfloat16_as_ushort(h1) << 16);
        *(unsigned*)(clo + obase + d) =
            (unsigned)__bfloat16_as_ushort(l0) | ((unsigned)__bfloat16_as_ushort(l1) << 16);
    }
}

// ---------------- CLS extraction + norm ----------------
__global__ void cls_kernel() {
    __shared__ float sred[9];
    int b = blockIdx.x;
    float loc = 0.f;
    #pragma unroll
    for (int i = 0; i < 3; i++) {
        int j = threadIdx.x + i * 256;
        float v = g_x[(size_t)(b * Ss) * Hh + j];
        g_cls[b * Hh + j] = v;
        loc += v * v;
    }
    float s = blk_sum256(loc, sred);
    if (threadIdx.x == 0) g_cn[b] = fmaxf(sqrtf(s), EPS_COS);
}

__global__ void reset_best_kernel() {
    if (threadIdx.x < Bb) g_best[threadIdx.x] = 0ull;
}

// ---------------- cosine + per-block argmax reduction ----------------
__global__ void __launch_bounds__(128) cos_kernel(const float* __restrict__ lab,
                                                  float* __restrict__ out) {
    __shared__ float clsS[Bb][33];
    __shared__ float sInvCn[Bb];
    int l = blockIdx.x * 128 + threadIdx.x;
    bool valid = (l < NLl);
    if (threadIdx.x < Bb) sInvCn[threadIdx.x] = 1.0f / g_cn[threadIdx.x];

    float acc[Bb];
    #pragma unroll
    for (int bb = 0; bb < Bb; bb++) acc[bb] = 0.f;

    for (int k0 = 0; k0 < Hh; k0 += 32) {
        #pragma unroll
        for (int i = 0; i < 8; i++) {
            int idx = threadIdx.x + i * 128;
            int bb = idx >> 5, kk = idx & 31;
            clsS[bb][kk] = g_cls[bb * Hh + k0 + kk];
        }
        __syncthreads();
        if (valid) {
            float lv[32];
            const float4* lp = (const float4*)(lab + (size_t)l * Hh + k0);
            #pragma unroll
            for (int i = 0; i < 8; i++) {
                float4 v4 = lp[i];
                lv[i * 4] = v4.x; lv[i * 4 + 1] = v4.y; lv[i * 4 + 2] = v4.z; lv[i * 4 + 3] = v4.w;
            }
            #pragma unroll
            for (int bb = 0; bb < Bb; bb++) {
                float a = acc[bb];
                #pragma unroll
                for (int kk = 0; kk < 32; kk++) a = fmaf(clsS[bb][kk], lv[kk], a);
                acc[bb] = a;
            }
        }
        __syncthreads();
    }

    float invl = 0.f;
    if (valid) {
        float s = 0.f;
        const float4* lp = (const float4*)(lab + (size_t)l * Hh);
        #pragma unroll 4
        for (int i = 0; i < Hh / 4; i++) {
            float4 v4 = lp[i];
            s += v4.x * v4.x + v4.y * v4.y + v4.z * v4.z + v4.w * v4.w;
        }
        invl = 1.0f / fmaxf(sqrtf(s), EPS_COS);
    }

    int lane = threadIdx.x & 31;
    #pragma unroll 1
    for (int bb = 0; bb < Bb; bb++) {
        unsigned long long key = 0ull;
        if (valid) {
            float c = acc[bb] * invl * sInvCn[bb];
            out[(size_t)bb * NLl + l] = c;
            key = pack_key(c, l);
        }
        #pragma unroll
        for (int o = 16; o > 0; o >>= 1) {
            unsigned long long other = __shfl_down_sync(0xffffffffu, key, o);
            key = (other > key) ? other : key;
        }
        if (lane == 0) atomicMax(&g_best[bb], key);
    }
}

__global__ void ids_out_kernel(float* __restrict__ out) {
    int b = threadIdx.x;
    if (b < Bb) {
        unsigned idpart = (unsigned)(g_best[b] & 0xFFFFFFFFull);
        out[(size_t)Bb * NLl + b] = (float)(0xFFFFFFFFu - idpart);
    }
}

// ---------------- host orchestration ----------------
extern "C" void kernel_launch(void* const* d_in, const int* in_sizes, int n_in,
                              void* d_out, int out_size) {
    const int*   ids  = (const int*)d_in[0];
    const int*   tys  = (const int*)d_in[1];
    const float* word = (const float*)d_in[2];
    const float* pos  = (const float*)d_in[3];
    const float* typ  = (const float*)d_in[4];
    const float* eg   = (const float*)d_in[5];
    const float* eb   = (const float*)d_in[6];
    const float* Wq   = (const float*)d_in[7];
    const float* bq   = (const float*)d_in[8];
    const float* Wk   = (const float*)d_in[9];
    const float* bk   = (const float*)d_in[10];
    const float* Wv   = (const float*)d_in[11];
    const float* bv   = (const float*)d_in[12];
    const float* Wo   = (const float*)d_in[13];
    const float* bo   = (const float*)d_in[14];
    const float* g1   = (const float*)d_in[15];
    const float* be1  = (const float*)d_in[16];
    const float* W1   = (const float*)d_in[17];
    const float* b1   = (const float*)d_in[18];
    const float* W2   = (const float*)d_in[19];
    const float* b2   = (const float*)d_in[20];
    const float* g2   = (const float*)d_in[21];
    const float* be2  = (const float*)d_in[22];
    const float* lab  = (const float*)d_in[23];
    float* out = (float*)d_out;

    float *px, *py, *pqkv, *pmbias, *pbqkv;
    __nv_bfloat16 *pxhi, *pxlo, *pchi, *pclo, *phhi, *phlo, *pwthi, *pwtlo;
    cudaGetSymbolAddress((void**)&px,    g_x);
    cudaGetSymbolAddress((void**)&py,    g_y);
    cudaGetSymbolAddress((void**)&pqkv,  g_qkv);
    cudaGetSymbolAddress((void**)&pmbias,g_mbias);
    cudaGetSymbolAddress((void**)&pbqkv, g_bqkv);
    cudaGetSymbolAddress((void**)&pxhi,  g_xhi);
    cudaGetSymbolAddress((void**)&pxlo,  g_xlo);
    cudaGetSymbolAddress((void**)&pchi,  g_chi);
    cudaGetSymbolAddress((void**)&pclo,  g_clo);
    cudaGetSymbolAddress((void**)&phhi,  g_hhi);
    cudaGetSymbolAddress((void**)&phlo,  g_hlo);
    cudaGetSymbolAddress((void**)&pwthi, g_wthi);
    cudaGetSymbolAddress((void**)&pwtlo, g_wtlo);

    const int attn_smem = (2 * Ss * DHh + Ss) * (int)sizeof(float);
    cudaFuncSetAttribute(attn_kernel, cudaFuncAttributeMaxDynamicSharedMemorySize, attn_smem);
    cudaFuncSetAttribute(gemm_mma<0>, cudaFuncAttributeMaxDynamicSharedMemorySize, GSMEM);
    cudaFuncSetAttribute(gemm_mma<1>, cudaFuncAttributeMaxDynamicSharedMemorySize, GSMEM);

    // weight transpose + split (inside timed region; ~150us)
    dim3 tb(32, 8);
    wsplit_kernel<<<dim3(Hh / 32, Hh / 32, Ll), tb>>>(Wq, 0, Hh, Hh);
    wsplit_kernel<<<dim3(Hh / 32, Hh / 32, Ll), tb>>>(Wk, (long)Hh * Hh, Hh, Hh);
    wsplit_kernel<<<dim3(Hh / 32, Hh / 32, Ll), tb>>>(Wv, (long)2 * Hh * Hh, Hh, Hh);
    wsplit_kernel<<<dim3(Hh / 32, Hh / 32, Ll), tb>>>(Wo, OFF_O, Hh, Hh);
    wsplit_kernel<<<dim3(FFf / 32, Hh / 32, Ll), tb>>>(W1, OFF_W1, Hh, FFf);
    wsplit_kernel<<<dim3(Hh / 32, FFf / 32, Ll), tb>>>(W2, OFF_W2, FFf, Hh);
    pack_bias_kernel<<<Ll, Hh>>>(bq, bk, bv);

    embed_ln_kernel<<<NTOK, 256>>>(ids, tys, word, pos, typ, eg, eb);

    for (int l = 0; l < Ll; l++) {
        size_t wl = (size_t)l * LSTRIDE;
        gemm_mma<0><<<dim3(QKVN / 128, 32), 256, GSMEM>>>(
            pxhi, pxlo, pwthi + wl, pwtlo + wl, pbqkv + l * QKVN,
            pqkv, nullptr, nullptr, Hh, QKVN);
        attn_kernel<<<Bb * NHh, 128, attn_smem>>>(pqkv, pmbias, pchi, pclo);
        gemm_mma<0><<<dim3(Hh / 128, 32), 256, GSMEM>>>(
            pchi, pclo, pwthi + wl + OFF_O, pwtlo + wl + OFF_O, bo + (size_t)l * Hh,
            py, nullptr, nullptr, Hh, Hh);
        add_ln_kernel<<<NTOK, 256>>>(px, py, g1 + (size_t)l * Hh, be1 + (size_t)l * Hh);
        gemm_mma<1><<<dim3(FFf / 128, 32), 256, GSMEM>>>(
            pxhi, pxlo, pwthi + wl + OFF_W1, pwtlo + wl + OFF_W1, b1 + (size_t)l * FFf,
            nullptr, phhi, phlo, Hh, FFf);
        gemm_mma<0><<<dim3(Hh / 128, 32), 256, GSMEM>>>(
            phhi, phlo, pwthi + wl + OFF_W2, pwtlo + wl + OFF_W2, b2 + (size_t)l * Hh,
            py, nullptr, nullptr, FFf, Hh);
        add_ln_kernel<<<NTOK, 256>>>(px, py, g2 + (size_t)l * Hh, be2 + (size_t)l * Hh);
    }

    cls_kernel<<<Bb, 256>>>();
    reset_best_kernel<<<1, 32>>>();
    cos_kernel<<<(NLl + 127) / 128, 128>>>(lab, out);
    if (out_size >= Bb * NLl + Bb) ids_out_kernel<<<1, 32>>>(out);
}

// round 4
// speedup vs baseline: 2.1088x; 1.0065x over previous
#include <cuda_runtime.h>
#include <cuda_bf16.h>
#include <math.h>
#include <cstdint>

// ---------------- problem constants ----------------
#define Vv   30522
#define Hh   768
#define Ll   12
#define FFf  3072
#define NHh  12
#define DHh  64
#define Bb   32
#define Ss   128
#define NLl  10000
#define NTOK (Bb*Ss)          // 4096
#define QKVN (3*Hh)           // 2304
#define EPS_LN  1e-12f
#define EPS_COS 1e-8f

// transposed split-weight layout per layer (element offsets)
#define OFF_O   (QKVN*Hh)             // after packed qkv [2304][768]
#define OFF_W1  (OFF_O + Hh*Hh)       // [3072][768]
#define OFF_W2  (OFF_W1 + Hh*FFf)     // [768][3072]
#define LSTRIDE (OFF_W2 + FFf*Hh)     // 7,077,888

// ---------------- device scratch ----------------
__device__ __nv_bfloat16 g_wthi[Ll*LSTRIDE];
__device__ __nv_bfloat16 g_wtlo[Ll*LSTRIDE];
__device__ float g_bqkv[Ll*QKVN];

__device__ float         g_x  [NTOK*Hh];
__device__ __nv_bfloat16 g_xhi[NTOK*Hh];
__device__ __nv_bfloat16 g_xlo[NTOK*Hh];
__device__ float         g_qkv[NTOK*QKVN];
__device__ __nv_bfloat16 g_chi[NTOK*Hh];
__device__ __nv_bfloat16 g_clo[NTOK*Hh];
__device__ __nv_bfloat16 g_hhi[NTOK*FFf];
__device__ __nv_bfloat16 g_hlo[NTOK*FFf];
__device__ float         g_y  [NTOK*Hh];
__device__ float g_mbias[NTOK];
__device__ float g_cls[Bb*Hh];
__device__ float g_cn [Bb];
__device__ unsigned long long g_best[Bb];

// ---------------- PTX helpers (compute_100-safe: mma.sync / ldmatrix / cp.async) ----------------
__device__ __forceinline__ uint32_t smem_u32(const void* p) {
    uint32_t a;
    asm("{ .reg .u64 t; cvta.to.shared.u64 t, %1; cvt.u32.u64 %0, t; }" : "=r"(a) : "l"(p));
    return a;
}
__device__ __forceinline__ void cp_async16(uint32_t dst, const void* src) {
    asm volatile("cp.async.cg.shared.global [%0], [%1], 16;" :: "r"(dst), "l"(src) : "memory");
}
#define CP_COMMIT() asm volatile("cp.async.commit_group;" ::: "memory")
#define CP_WAIT(n)  asm volatile("cp.async.wait_group %0;" :: "n"(n) : "memory")

__device__ __forceinline__ void ldsm4(uint32_t& r0, uint32_t& r1, uint32_t& r2, uint32_t& r3,
                                      uint32_t addr) {
    asm volatile("ldmatrix.sync.aligned.m8n8.x4.shared.b16 {%0,%1,%2,%3}, [%4];"
                 : "=r"(r0), "=r"(r1), "=r"(r2), "=r"(r3) : "r"(addr));
}
__device__ __forceinline__ void mma16816(float* c, uint32_t a0, uint32_t a1, uint32_t a2,
                                         uint32_t a3, uint32_t b0, uint32_t b1) {
    asm volatile(
        "mma.sync.aligned.m16n8k16.row.col.f32.bf16.bf16.f32 "
        "{%0,%1,%2,%3}, {%4,%5,%6,%7}, {%8,%9}, {%0,%1,%2,%3};"
        : "+f"(c[0]), "+f"(c[1]), "+f"(c[2]), "+f"(c[3])
        : "r"(a0), "r"(a1), "r"(a2), "r"(a3), "r"(b0), "r"(b1));
}

// ---------------- misc helpers ----------------
__device__ __forceinline__ float blk_sum256(float v, volatile float* sred) {
    int lane = threadIdx.x & 31, w = threadIdx.x >> 5;
    #pragma unroll
    for (int o = 16; o > 0; o >>= 1) v += __shfl_down_sync(0xffffffffu, v, o);
    if (lane == 0) sred[w] = v;
    __syncthreads();
    if (threadIdx.x == 0) {
        float s = 0.f;
        #pragma unroll
        for (int i = 0; i < 8; i++) s += sred[i];
        sred[8] = s;
    }
    __syncthreads();
    float r = sred[8];
    __syncthreads();
    return r;
}
__device__ __forceinline__ float gelu_tanh(float x) {
    float x3 = x * x * x;
    float t = tanhf(0.7978845608028654f * (x + 0.044715f * x3));
    return 0.5f * x * (1.0f + t);
}
__device__ __forceinline__ unsigned long long pack_key(float c, int l) {
    unsigned u = __float_as_uint(c);
    u = (u & 0x80000000u) ? ~u : (u | 0x80000000u);
    return ((unsigned long long)u << 32) | (unsigned long long)(0xFFFFFFFFu - (unsigned)l);
}
__device__ __forceinline__ void split_store(float v, __nv_bfloat16* hi, __nv_bfloat16* lo) {
    __nv_bfloat16 h = __float2bfloat16(v);
    *hi = h;
    *lo = __float2bfloat16(v - __bfloat162float(h));
}

// ---------------- weight transpose + bf16 split ----------------
__global__ void wsplit_kernel(const float* __restrict__ W, long dstOff, int K, int N) {
    __shared__ float t[32][33];
    int l = blockIdx.z;
    const float* Ws = W + (size_t)l * K * N;
    __nv_bfloat16* th = g_wthi + (size_t)l * LSTRIDE + dstOff;
    __nv_bfloat16* tl = g_wtlo + (size_t)l * LSTRIDE + dstOff;
    int n = blockIdx.x * 32 + threadIdx.x;
    #pragma unroll
    for (int i = 0; i < 4; i++) {
        int k = blockIdx.y * 32 + threadIdx.y + i * 8;
        t[threadIdx.y + i * 8][threadIdx.x] = Ws[(size_t)k * N + n];
    }
    __syncthreads();
    int k2 = blockIdx.y * 32 + threadIdx.x;
    #pragma unroll
    for (int i = 0; i < 4; i++) {
        int n2 = blockIdx.x * 32 + threadIdx.y + i * 8;
        float v = t[threadIdx.x][threadIdx.y + i * 8];
        split_store(v, &th[(size_t)n2 * K + k2], &tl[(size_t)n2 * K + k2]);
    }
}

__global__ void pack_bias_kernel(const float* __restrict__ bq, const float* __restrict__ bk,
                                 const float* __restrict__ bv) {
    int l = blockIdx.x, j = threadIdx.x;
    g_bqkv[l * QKVN + j]          = bq[l * Hh + j];
    g_bqkv[l * QKVN + Hh + j]     = bk[l * Hh + j];
    g_bqkv[l * QKVN + 2 * Hh + j] = bv[l * Hh + j];
}

// ---------------- embeddings + LN + mask bias ----------------
__global__ void embed_ln_kernel(const int* __restrict__ ids, const int* __restrict__ tys,
                                const float* __restrict__ word, const float* __restrict__ pos,
                                const float* __restrict__ typ,
                                const float* __restrict__ eg, const float* __restrict__ eb) {
    __shared__ float sred[9];
    int t = blockIdx.x;
    int s = t & (Ss - 1);
    int id = ids[t], ty = tys[t];
    float v[3];
    float loc = 0.f;
    #pragma unroll
    for (int i = 0; i < 3; i++) {
        int j = threadIdx.x + i * 256;
        v[i] = word[(size_t)id * Hh + j] + pos[(size_t)s * Hh + j] + typ[(size_t)ty * Hh + j];
        loc += v[i];
    }
    float mu = blk_sum256(loc, sred) * (1.0f / Hh);
    float l2 = 0.f;
    #pragma unroll
    for (int i = 0; i < 3; i++) { float d = v[i] - mu; l2 += d * d; }
    float var = blk_sum256(l2, sred) * (1.0f / Hh);
    float rstd = rsqrtf(var + EPS_LN);
    #pragma unroll
    for (int i = 0; i < 3; i++) {
        int j = threadIdx.x + i * 256;
        size_t idx = (size_t)t * Hh + j;
        float o = (v[i] - mu) * rstd * eg[j] + eb[j];
        g_x[idx] = o;
        split_store(o, &g_xhi[idx], &g_xlo[idx]);
    }
    if (threadIdx.x == 0) g_mbias[t] = (id > 0) ? 0.f : -10000.0f;
}

// ---------------- residual add + LN (in place on x), fused bf16 split ----------------
__global__ void add_ln_kernel(float* __restrict__ x, const float* __restrict__ y,
                              const float* __restrict__ g, const float* __restrict__ b) {
    __shared__ float sred[9];
    size_t base = (size_t)blockIdx.x * Hh;
    float v[3];
    float loc = 0.f;
    #pragma unroll
    for (int i = 0; i < 3; i++) {
        int j = threadIdx.x + i * 256;
        v[i] = x[base + j] + y[base + j];
        loc += v[i];
    }
    float mu = blk_sum256(loc, sred) * (1.0f / Hh);
    float l2 = 0.f;
    #pragma unroll
    for (int i = 0; i < 3; i++) { float d = v[i] - mu; l2 += d * d; }
    float var = blk_sum256(l2, sred) * (1.0f / Hh);
    float rstd = rsqrtf(var + EPS_LN);
    #pragma unroll
    for (int i = 0; i < 3; i++) {
        int j = threadIdx.x + i * 256;
        float o = (v[i] - mu) * rstd * g[j] + b[j];
        x[base + j] = o;
        split_store(o, &g_xhi[base + j], &g_xlo[base + j]);
    }
}

// ---------------- HMMA split-bf16 GEMM: C[4096, N] = A @ W^T + bias ----------------
// CTA: 128x128 tile, K-chunk 32, double-buffered cp.async, 8 warps (warp tile 64x32).
// 3 Markidis terms: AhBh + AlBh + AhBl (fp32 accum).  2 CTAs/SM via launch_bounds.
#define GT_TILE  (128 * 80)        // bytes per sub-tile
#define GT_STAGE (4 * GT_TILE)     // 40960
#define GSMEM    (2 * GT_STAGE)    // 81920
template <int OUTMODE>
__global__ void __launch_bounds__(256, 2) gemm_mma(
    const __nv_bfloat16* __restrict__ Ahi, const __nv_bfloat16* __restrict__ Alo,
    const __nv_bfloat16* __restrict__ Bhi, const __nv_bfloat16* __restrict__ Blo,
    const float* __restrict__ bias,
    float* __restrict__ Cf, __nv_bfloat16* __restrict__ Chi, __nv_bfloat16* __restrict__ Clo,
    int K, int ldc)
{
    extern __shared__ char sm[];
    const uint32_t sb = smem_u32(sm);
    int tid = threadIdx.x, lane = tid & 31, wid = tid >> 5;
    int wm = wid >> 2, wn = wid & 3;              // warp tile: rows wm*64, cols wn*32
    int m0 = blockIdx.y * 128, n0 = blockIdx.x * 128;

    // ldmatrix lane offsets
    int q = lane >> 3, r = lane & 7;
    uint32_t aLane = (uint32_t)(((q & 1) * 8 + r) * 80 + (q >> 1) * 16);
    uint32_t bLane = (uint32_t)(((q >> 1) * 8 + r) * 80 + (q & 1) * 16);

    float acc[4][4][4];
    #pragma unroll
    for (int mi = 0; mi < 4; mi++)
        #pragma unroll
        for (int ni = 0; ni < 4; ni++)
            #pragma unroll
            for (int e = 0; e < 4; e++) acc[mi][ni][e] = 0.f;

    int l_hl  = tid >> 7;
    int l_row = (tid >> 1) & 63;
    int l_seg = tid & 1;

    int nchunk = K >> 5;

    auto load_stage = [&](int c) {
        int k0 = c << 5;
        uint32_t base = sb + (uint32_t)(c & 1) * GT_STAGE;
        #pragma unroll
        for (int i = 0; i < 2; i++) {
            int row = l_row + i * 64;
            #pragma unroll
            for (int j = 0; j < 2; j++) {
                int seg = l_seg + j * 2;
                uint32_t off = (uint32_t)(row * 80 + seg * 16);
                const __nv_bfloat16* asrc =
                    (l_hl ? Alo : Ahi) + (size_t)(m0 + row) * K + k0 + seg * 8;
                const __nv_bfloat16* bsrc =
                    (l_hl ? Blo : Bhi) + (size_t)(n0 + row) * K + k0 + seg * 8;
                cp_async16(base + (uint32_t)l_hl * GT_TILE + off, asrc);
                cp_async16(base + (uint32_t)(2 + l_hl) * GT_TILE + off, bsrc);
            }
        }
    };

    load_stage(0);
    CP_COMMIT();

    for (int c = 0; c < nchunk; c++) {
        if (c + 1 < nchunk) { load_stage(c + 1); CP_COMMIT(); CP_WAIT(1); }
        else { CP_WAIT(0); }
        __syncthreads();

        uint32_t base = sb + (uint32_t)(c & 1) * GT_STAGE;
        uint32_t aBaseH = base + (uint32_t)((wm * 64) * 80) + aLane;
        uint32_t aBaseL = aBaseH + GT_TILE;
        uint32_t bBaseH = base + 2 * GT_TILE + (uint32_t)((wn * 32) * 80) + bLane;
        uint32_t bBaseL = bBaseH + GT_TILE;

        #pragma unroll
        for (int ks = 0; ks < 2; ks++) {
            uint32_t ko = (uint32_t)(ks * 32);
            uint32_t ah[4][4], al[4][4], bf[2][4];
            #pragma unroll
            for (int mi = 0; mi < 4; mi++)
                ldsm4(ah[mi][0], ah[mi][1], ah[mi][2], ah[mi][3],
                      aBaseH + (uint32_t)(mi * 16 * 80) + ko);
            #pragma unroll
            for (int mi = 0; mi < 4; mi++)
                ldsm4(al[mi][0], al[mi][1], al[mi][2], al[mi][3],
                      aBaseL + (uint32_t)(mi * 16 * 80) + ko);
            #pragma unroll
            for (int p = 0; p < 2; p++)
                ldsm4(bf[p][0], bf[p][1], bf[p][2], bf[p][3],
                      bBaseH + (uint32_t)(p * 16 * 80) + ko);
            #pragma unroll
            for (int mi = 0; mi < 4; mi++)
                #pragma unroll
                for (int ni = 0; ni < 4; ni++) {
                    int p = ni >> 1, su = ni & 1;
                    mma16816(acc[mi][ni], ah[mi][0], ah[mi][1], ah[mi][2], ah[mi][3],
                             bf[p][su * 2], bf[p][su * 2 + 1]);
                }
            #pragma unroll
            for (int mi = 0; mi < 4; mi++)
                #pragma unroll
                for (int ni = 0; ni < 4; ni++) {
                    int p = ni >> 1, su = ni & 1;
                    mma16816(acc[mi][ni], al[mi][0], al[mi][1], al[mi][2], al[mi][3],
                             bf[p][su * 2], bf[p][su * 2 + 1]);
                }
            #pragma unroll
            for (int p = 0; p < 2; p++)
                ldsm4(bf[p][0], bf[p][1], bf[p][2], bf[p][3],
                      bBaseL + (uint32_t)(p * 16 * 80) + ko);
            #pragma unroll
            for (int mi = 0; mi < 4; mi++)
                #pragma unroll
                for (int ni = 0; ni < 4; ni++) {
                    int p = ni >> 1, su = ni & 1;
                    mma16816(acc[mi][ni], ah[mi][0], ah[mi][1], ah[mi][2], ah[mi][3],
                             bf[p][su * 2], bf[p][su * 2 + 1]);
                }
        }
        __syncthreads();
    }

    // ---------------- epilogue ----------------
    int rbase = m0 + wm * 64 + (lane >> 2);
    int cbase = n0 + wn * 32 + (lane & 3) * 2;
    #pragma unroll
    for (int mi = 0; mi < 4; mi++) {
        #pragma unroll
        for (int ni = 0; ni < 4; ni++) {
            int row = rbase + mi * 16;
            int col = cbase + ni * 8;
            float b0 = bias[col], b1 = bias[col + 1];
            float v0 = acc[mi][ni][0] + b0, v1 = acc[mi][ni][1] + b1;
            float v2 = acc[mi][ni][2] + b0, v3 = acc[mi][ni][3] + b1;
            if (OUTMODE == 0) {
                *(float2*)(Cf + (size_t)row * ldc + col)       = make_float2(v0, v1);
                *(float2*)(Cf + (size_t)(row + 8) * ldc + col) = make_float2(v2, v3);
            } else {
                v0 = gelu_tanh(v0); v1 = gelu_tanh(v1);
                v2 = gelu_tanh(v2); v3 = gelu_tanh(v3);
                __nv_bfloat16 h0 = __float2bfloat16(v0), h1 = __float2bfloat16(v1);
                __nv_bfloat16 h2 = __float2bfloat16(v2), h3 = __float2bfloat16(v3);
                __nv_bfloat16 l0 = __float2bfloat16(v0 - __bfloat162float(h0));
                __nv_bfloat16 l1 = __float2bfloat16(v1 - __bfloat162float(h1));
                __nv_bfloat16 l2 = __float2bfloat16(v2 - __bfloat162float(h2));
                __nv_bfloat16 l3 = __float2bfloat16(v3 - __bfloat162float(h3));
                *(unsigned*)(Chi + (size_t)row * ldc + col) =
                    (unsigned)__bfloat16_as_ushort(h0) | ((unsigned)__bfloat16_as_ushort(h1) << 16);
                *(unsigned*)(Clo + (size_t)row * ldc + col) =
                    (unsigned)__bfloat16_as_ushort(l0) | ((unsigned)__bfloat16_as_ushort(l1) << 16);
                *(unsigned*)(Chi + (size_t)(row + 8) * ldc + col) =
                    (unsigned)__bfloat16_as_ushort(h2) | ((unsigned)__bfloat16_as_ushort(h3) << 16);
                *(unsigned*)(Clo + (size_t)(row + 8) * ldc + col) =
                    (unsigned)__bfloat16_as_ushort(l2) | ((unsigned)__bfloat16_as_ushort(l3) << 16);
            }
        }
    }
}

// ---------------- attention: one-pass, scores cached in smem ----------------
// smem: Ks[128][64] + Vs[128][64] + S[128][129] (padded rows -> conflict-free) + bias[128]
#define ATTN_SMEM ((2*Ss*DHh + Ss*129 + Ss) * (int)sizeof(float))
__global__ void __launch_bounds__(128) attn_kernel(const float* __restrict__ Qkv,
                                                   const float* __restrict__ bias,
                                                   __nv_bfloat16* __restrict__ chi,
                                                   __nv_bfloat16* __restrict__ clo) {
    extern __shared__ float smf[];
    float* Ks = smf;                       // [128][64]
    float* Vs = smf + Ss * DHh;            // [128][64]
    float* S  = smf + 2 * Ss * DHh;        // [128][129]
    float* biasS = S + Ss * 129;           // [128]
    int bn = blockIdx.x;
    int b = bn / NHh, n = bn % NHh;
    int tid = threadIdx.x;
    const float scale = 0.125f;

    #pragma unroll
    for (int i = 0; i < 16; i++) {
        int linr = tid + i * 128;
        int j = linr >> 4, c4 = (linr & 15) * 4;
        size_t rowb = (size_t)(b * Ss + j) * QKVN + n * DHh + c4;
        *(float4*)&Ks[j * DHh + c4] = *(const float4*)(Qkv + rowb + Hh);
        *(float4*)&Vs[j * DHh + c4] = *(const float4*)(Qkv + rowb + 2 * Hh);
    }
    biasS[tid] = bias[b * Ss + tid];
    __syncthreads();

    int qi = tid;
    float Qr[DHh];
    const float4* qp = (const float4*)(Qkv + (size_t)(b * Ss + qi) * QKVN + n * DHh);
    #pragma unroll
    for (int i = 0; i < 16; i++) {
        float4 v4 = qp[i];
        Qr[i * 4 + 0] = v4.x; Qr[i * 4 + 1] = v4.y; Qr[i * 4 + 2] = v4.z; Qr[i * 4 + 3] = v4.w;
    }

    float* Srow = S + qi * 129;
    float m = -1e30f;
    // single QK pass: scores to smem, track max (K reads are warp-uniform broadcasts)
    #pragma unroll 1
    for (int j = 0; j < Ss; j += 4) {
        const float* k0 = Ks + j * DHh;
        float s0 = 0.f, s1 = 0.f, s2 = 0.f, s3 = 0.f;
        #pragma unroll
        for (int d = 0; d < DHh; d++) {
            float qd = Qr[d];
            s0 = fmaf(qd, k0[d], s0);
            s1 = fmaf(qd, k0[DHh + d], s1);
            s2 = fmaf(qd, k0[2 * DHh + d], s2);
            s3 = fmaf(qd, k0[3 * DHh + d], s3);
        }
        s0 = fmaf(s0, scale, biasS[j]);
        s1 = fmaf(s1, scale, biasS[j + 1]);
        s2 = fmaf(s2, scale, biasS[j + 2]);
        s3 = fmaf(s3, scale, biasS[j + 3]);
        Srow[j] = s0; Srow[j + 1] = s1; Srow[j + 2] = s2; Srow[j + 3] = s3;
        m = fmaxf(m, fmaxf(fmaxf(s0, s1), fmaxf(s2, s3)));
    }
    // exp + sum (in place)
    float lsum = 0.f;
    #pragma unroll 4
    for (int j = 0; j < Ss; j++) {
        float p = __expf(Srow[j] - m);
        Srow[j] = p;
        lsum += p;
    }
    float inv_l = 1.0f / lsum;

    // PV (V reads are warp-uniform broadcasts, p reads conflict-free via 129-pad)
    float acc[DHh];
    #pragma unroll
    for (int d = 0; d < DHh; d++) acc[d] = 0.f;
    #pragma unroll 1
    for (int j = 0; j < Ss; j++) {
        float p = Srow[j];
        const float* vr = Vs + j * DHh;
        #pragma unroll
        for (int d = 0; d < DHh; d++) acc[d] = fmaf(p, vr[d], acc[d]);
    }
    size_t obase = (size_t)(b * Ss + qi) * Hh + n * DHh;
    #pragma unroll
    for (int d = 0; d < DHh; d += 2) {
        float v0 = acc[d] * inv_l, v1 = acc[d + 1] * inv_l;
        __nv_bfloat16 h0 = __float2bfloat16(v0);
        __nv_bfloat16 h1 = __float2bfloat16(v1);
        __nv_bfloat16 l0 = __float2bfloat16(v0 - __bfloat162float(h0));
        __nv_bfloat16 l1 = __float2bfloat16(v1 - __bfloat162float(h1));
        *(unsigned*)(chi + obase + d) =
            (unsigned)__bfloat16_as_ushort(h0) | ((unsigned)__bfloat16_as_ushort(h1) << 16);
        *(unsigned*)(clo + obase + d) =
            (unsigned)__bfloat16_as_ushort(l0) | ((unsigned)__bfloat16_as_ushort(l1) << 16);
    }
}

// ---------------- CLS extraction + norm ----------------
__global__ void cls_kernel() {
    __shared__ float sred[9];
    int b = blockIdx.x;
    float loc = 0.f;
    #pragma unroll
    for (int i = 0; i < 3; i++) {
        int j = threadIdx.x + i * 256;
        float v = g_x[(size_t)(b * Ss) * Hh + j];
        g_cls[b * Hh + j] = v;
        loc += v * v;
    }
    float s = blk_sum256(loc, sred);
    if (threadIdx.x == 0) g_cn[b] = fmaxf(sqrtf(s), EPS_COS);
}

__global__ void reset_best_kernel() {
    if (threadIdx.x < Bb) g_best[threadIdx.x] = 0ull;
}

// ---------------- cosine + per-block argmax reduction ----------------
__global__ void __launch_bounds__(128) cos_kernel(const float* __restrict__ lab,
                                                  float* __restrict__ out) {
    __shared__ float clsS[Bb][33];
    __shared__ float sInvCn[Bb];
    int l = blockIdx.x * 128 + threadIdx.x;
    bool valid = (l < NLl);
    if (threadIdx.x < Bb) sInvCn[threadIdx.x] = 1.0f / g_cn[threadIdx.x];

    float acc[Bb];
    #pragma unroll
    for (int bb = 0; bb < Bb; bb++) acc[bb] = 0.f;

    for (int k0 = 0; k0 < Hh; k0 += 32) {
        #pragma unroll
        for (int i = 0; i < 8; i++) {
            int idx = threadIdx.x + i * 128;
            int bb = idx >> 5, kk = idx & 31;
            clsS[bb][kk] = g_cls[bb * Hh + k0 + kk];
        }
        __syncthreads();
        if (valid) {
            float lv[32];
            const float4* lp = (const float4*)(lab + (size_t)l * Hh + k0);
            #pragma unroll
            for (int i = 0; i < 8; i++) {
                float4 v4 = lp[i];
                lv[i * 4] = v4.x; lv[i * 4 + 1] = v4.y; lv[i * 4 + 2] = v4.z; lv[i * 4 + 3] = v4.w;
            }
            #pragma unroll
            for (int bb = 0; bb < Bb; bb++) {
                float a = acc[bb];
                #pragma unroll
                for (int kk = 0; kk < 32; kk++) a = fmaf(clsS[bb][kk], lv[kk], a);
                acc[bb] = a;
            }
        }
        __syncthreads();
    }

    float invl = 0.f;
    if (valid) {
        float s = 0.f;
        const float4* lp = (const float4*)(lab + (size_t)l * Hh);
        #pragma unroll 4
        for (int i = 0; i < Hh / 4; i++) {
            float4 v4 = lp[i];
            s += v4.x * v4.x + v4.y * v4.y + v4.z * v4.z + v4.w * v4.w;
        }
        invl = 1.0f / fmaxf(sqrtf(s), EPS_COS);
    }

    int lane = threadIdx.x & 31;
    #pragma unroll 1
    for (int bb = 0; bb < Bb; bb++) {
        unsigned long long key = 0ull;
        if (valid) {
            float c = acc[bb] * invl * sInvCn[bb];
            out[(size_t)bb * NLl + l] = c;
            key = pack_key(c, l);
        }
        #pragma unroll
        for (int o = 16; o > 0; o >>= 1) {
            unsigned long long other = __shfl_down_sync(0xffffffffu, key, o);
            key = (other > key) ? other : key;
        }
        if (lane == 0) atomicMax(&g_best[bb], key);
    }
}

__global__ void ids_out_kernel(float* __restrict__ out) {
    int b = threadIdx.x;
    if (b < Bb) {
        unsigned idpart = (unsigned)(g_best[b] & 0xFFFFFFFFull);
        out[(size_t)Bb * NLl + b] = (float)(0xFFFFFFFFu - idpart);
    }
}

// ---------------- host orchestration ----------------
extern "C" void kernel_launch(void* const* d_in, const int* in_sizes, int n_in,
                              void* d_out, int out_size) {
    const int*   ids  = (const int*)d_in[0];
    const int*   tys  = (const int*)d_in[1];
    const float* word = (const float*)d_in[2];
    const float* pos  = (const float*)d_in[3];
    const float* typ  = (const float*)d_in[4];
    const float* eg   = (const float*)d_in[5];
    const float* eb   = (const float*)d_in[6];
    const float* Wq   = (const float*)d_in[7];
    const float* bq   = (const float*)d_in[8];
    const float* Wk   = (const float*)d_in[9];
    const float* bk   = (const float*)d_in[10];
    const float* Wv   = (const float*)d_in[11];
    const float* bv   = (const float*)d_in[12];
    const float* Wo   = (const float*)d_in[13];
    const float* bo   = (const float*)d_in[14];
    const float* g1   = (const float*)d_in[15];
    const float* be1  = (const float*)d_in[16];
    const float* W1   = (const float*)d_in[17];
    const float* b1   = (const float*)d_in[18];
    const float* W2   = (const float*)d_in[19];
    const float* b2   = (const float*)d_in[20];
    const float* g2   = (const float*)d_in[21];
    const float* be2  = (const float*)d_in[22];
    const float* lab  = (const float*)d_in[23];
    float* out = (float*)d_out;

    float *px, *py, *pqkv, *pmbias, *pbqkv;
    __nv_bfloat16 *pxhi, *pxlo, *pchi, *pclo, *phhi, *phlo, *pwthi, *pwtlo;
    cudaGetSymbolAddress((void**)&px,    g_x);
    cudaGetSymbolAddress((void**)&py,    g_y);
    cudaGetSymbolAddress((void**)&pqkv,  g_qkv);
    cudaGetSymbolAddress((void**)&pmbias,g_mbias);
    cudaGetSymbolAddress((void**)&pbqkv, g_bqkv);
    cudaGetSymbolAddress((void**)&pxhi,  g_xhi);
    cudaGetSymbolAddress((void**)&pxlo,  g_xlo);
    cudaGetSymbolAddress((void**)&pchi,  g_chi);
    cudaGetSymbolAddress((void**)&pclo,  g_clo);
    cudaGetSymbolAddress((void**)&phhi,  g_hhi);
    cudaGetSymbolAddress((void**)&phlo,  g_hlo);
    cudaGetSymbolAddress((void**)&pwthi, g_wthi);
    cudaGetSymbolAddress((void**)&pwtlo, g_wtlo);

    cudaFuncSetAttribute(attn_kernel, cudaFuncAttributeMaxDynamicSharedMemorySize, ATTN_SMEM);
    cudaFuncSetAttribute(gemm_mma<0>, cudaFuncAttributeMaxDynamicSharedMemorySize, GSMEM);
    cudaFuncSetAttribute(gemm_mma<1>, cudaFuncAttributeMaxDynamicSharedMemorySize, GSMEM);

    // weight transpose + split (inside timed region; ~150us)
    dim3 tb(32, 8);
    wsplit_kernel<<<dim3(Hh / 32, Hh / 32, Ll), tb>>>(Wq, 0, Hh, Hh);
    wsplit_kernel<<<dim3(Hh / 32, Hh / 32, Ll), tb>>>(Wk, (long)Hh * Hh, Hh, Hh);
    wsplit_kernel<<<dim3(Hh / 32, Hh / 32, Ll), tb>>>(Wv, (long)2 * Hh * Hh, Hh, Hh);
    wsplit_kernel<<<dim3(Hh / 32, Hh / 32, Ll), tb>>>(Wo, OFF_O, Hh, Hh);
    wsplit_kernel<<<dim3(FFf / 32, Hh / 32, Ll), tb>>>(W1, OFF_W1, Hh, FFf);
    wsplit_kernel<<<dim3(Hh / 32, FFf / 32, Ll), tb>>>(W2, OFF_W2, FFf, Hh);
    pack_bias_kernel<<<Ll, Hh>>>(bq, bk, bv);

    embed_ln_kernel<<<NTOK, 256>>>(ids, tys, word, pos, typ, eg, eb);

    for (int l = 0; l < Ll; l++) {
        size_t wl = (size_t)l * LSTRIDE;
        gemm_mma<0><<<dim3(QKVN / 128, 32), 256, GSMEM>>>(
            pxhi, pxlo, pwthi + wl, pwtlo + wl, pbqkv + l * QKVN,
            pqkv, nullptr, nullptr, Hh, QKVN);
        attn_kernel<<<Bb * NHh, 128, ATTN_SMEM>>>(pqkv, pmbias, pchi, pclo);
        gemm_mma<0><<<dim3(Hh / 128, 32), 256, GSMEM>>>(
            pchi, pclo, pwthi + wl + OFF_O, pwtlo + wl + OFF_O, bo + (size_t)l * Hh,
            py, nullptr, nullptr, Hh, Hh);
        add_ln_kernel<<<NTOK, 256>>>(px, py, g1 + (size_t)l * Hh, be1 + (size_t)l * Hh);
        gemm_mma<1><<<dim3(FFf / 128, 32), 256, GSMEM>>>(
            pxhi, pxlo, pwthi + wl + OFF_W1, pwtlo + wl + OFF_W1, b1 + (size_t)l * FFf,
            nullptr, phhi, phlo, Hh, FFf);
        gemm_mma<0><<<dim3(Hh / 128, 32), 256, GSMEM>>>(
            phhi, phlo, pwthi + wl + OFF_W2, pwtlo + wl + OFF_W2, b2 + (size_t)l * Hh,
            py, nullptr, nullptr, FFf, Hh);
        add_ln_kernel<<<NTOK, 256>>>(px, py, g2 + (size_t)l * Hh, be2 + (size_t)l * Hh);
    }

    cls_kernel<<<Bb, 256>>>();
    reset_best_kernel<<<1, 32>>>();
    cos_kernel<<<(NLl + 127) / 128, 128>>>(lab, out);
    if (out_size >= Bb * NLl + Bb) ids_out_kernel<<<1, 32>>>(out);
}

// round 5
// speedup vs baseline: 3.2528x; 1.5425x over previous
#include <cuda_runtime.h>
#include <cuda_fp16.h>
#include <math.h>
#include <cstdint>

// ---------------- problem constants ----------------
#define Vv   30522
#define Hh   768
#define Ll   12
#define FFf  3072
#define NHh  12
#define DHh  64
#define Bb   32
#define Ss   128
#define NLl  10000
#define NTOK (Bb*Ss)          // 4096
#define QKVN (3*Hh)           // 2304
#define EPS_LN  1e-12f
#define EPS_COS 1e-8f

// transposed fp16 weight layout per layer (element offsets)
#define OFF_O   (QKVN*Hh)             // after packed qkv [2304][768]
#define OFF_W1  (OFF_O + Hh*Hh)       // [3072][768]
#define OFF_W2  (OFF_W1 + Hh*FFf)     // [768][3072]
#define LSTRIDE (OFF_W2 + FFf*Hh)     // 7,077,888

// ---------------- device scratch ----------------
__device__ __half g_wth[Ll*LSTRIDE];           // fp16 weights, transposed [N][K]
__device__ float  g_bqkv[Ll*QKVN];

__device__ float  g_x  [NTOK*Hh];
__device__ __half g_xhi[NTOK*Hh];
__device__ __half g_xlo[NTOK*Hh];
__device__ float  g_qkv[NTOK*QKVN];
__device__ __half g_chi[NTOK*Hh];
__device__ __half g_clo[NTOK*Hh];
__device__ __half g_hhi[NTOK*FFf];
__device__ __half g_hlo[NTOK*FFf];
__device__ float  g_y  [NTOK*Hh];
__device__ float g_mbias[NTOK];
__device__ float g_cls[Bb*Hh];
__device__ float g_cn [Bb];
__device__ unsigned long long g_best[Bb];

// ---------------- PTX helpers (compute_100-safe) ----------------
__device__ __forceinline__ uint32_t smem_u32(const void* p) {
    uint32_t a;
    asm("{ .reg .u64 t; cvta.to.shared.u64 t, %1; cvt.u32.u64 %0, t; }" : "=r"(a) : "l"(p));
    return a;
}
__device__ __forceinline__ void cp_async16(uint32_t dst, const void* src) {
    asm volatile("cp.async.cg.shared.global [%0], [%1], 16;" :: "r"(dst), "l"(src) : "memory");
}
#define CP_COMMIT() asm volatile("cp.async.commit_group;" ::: "memory")
#define CP_WAIT(n)  asm volatile("cp.async.wait_group %0;" :: "n"(n) : "memory")

__device__ __forceinline__ void ldsm4(uint32_t& r0, uint32_t& r1, uint32_t& r2, uint32_t& r3,
                                      uint32_t addr) {
    asm volatile("ldmatrix.sync.aligned.m8n8.x4.shared.b16 {%0,%1,%2,%3}, [%4];"
                 : "=r"(r0), "=r"(r1), "=r"(r2), "=r"(r3) : "r"(addr));
}
__device__ __forceinline__ void mma16816(float* c, uint32_t a0, uint32_t a1, uint32_t a2,
                                         uint32_t a3, uint32_t b0, uint32_t b1) {
    asm volatile(
        "mma.sync.aligned.m16n8k16.row.col.f32.f16.f16.f32 "
        "{%0,%1,%2,%3}, {%4,%5,%6,%7}, {%8,%9}, {%0,%1,%2,%3};"
        : "+f"(c[0]), "+f"(c[1]), "+f"(c[2]), "+f"(c[3])
        : "r"(a0), "r"(a1), "r"(a2), "r"(a3), "r"(b0), "r"(b1));
}

// ---------------- misc helpers ----------------
__device__ __forceinline__ float blk_sum256(float v, volatile float* sred) {
    int lane = threadIdx.x & 31, w = threadIdx.x >> 5;
    #pragma unroll
    for (int o = 16; o > 0; o >>= 1) v += __shfl_down_sync(0xffffffffu, v, o);
    if (lane == 0) sred[w] = v;
    __syncthreads();
    if (threadIdx.x == 0) {
        float s = 0.f;
        #pragma unroll
        for (int i = 0; i < 8; i++) s += sred[i];
        sred[8] = s;
    }
    __syncthreads();
    float r = sred[8];
    __syncthreads();
    return r;
}
__device__ __forceinline__ float gelu_tanh(float x) {
    float x3 = x * x * x;
    float t = tanhf(0.7978845608028654f * (x + 0.044715f * x3));
    return 0.5f * x * (1.0f + t);
}
__device__ __forceinline__ unsigned long long pack_key(float c, int l) {
    unsigned u = __float_as_uint(c);
    u = (u & 0x80000000u) ? ~u : (u | 0x80000000u);
    return ((unsigned long long)u << 32) | (unsigned long long)(0xFFFFFFFFu - (unsigned)l);
}
__device__ __forceinline__ void split_store_h(float v, __half* hi, __half* lo) {
    __half h = __float2half(v);
    *hi = h;
    *lo = __float2half(v - __half2float(h));
}
__device__ __forceinline__ unsigned pack2h(float v0, float v1) {
    __half h0 = __float2half(v0), h1 = __float2half(v1);
    return (unsigned)__half_as_ushort(h0) | ((unsigned)__half_as_ushort(h1) << 16);
}

// ---------------- weight transpose to fp16 ----------------
// 4 matrices of [L][768][768]: Wq, Wk, Wv (packed qkv), Wo
__global__ void wsplit4_kernel(const float* __restrict__ W0, const float* __restrict__ W1m,
                               const float* __restrict__ W2m, const float* __restrict__ W3m) {
    __shared__ float t[32][33];
    int z = blockIdx.z;
    int m = z & 3, l = z >> 2;
    const float* Ws = (m == 0 ? W0 : m == 1 ? W1m : m == 2 ? W2m : W3m) + (size_t)l * Hh * Hh;
    long dstOff = (m < 3) ? (long)m * Hh * Hh : (long)OFF_O;
    __half* th = g_wth + (size_t)l * LSTRIDE + dstOff;
    int n = blockIdx.x * 32 + threadIdx.x;
    #pragma unroll
    for (int i = 0; i < 4; i++) {
        int k = blockIdx.y * 32 + threadIdx.y + i * 8;
        t[threadIdx.y + i * 8][threadIdx.x] = Ws[(size_t)k * Hh + n];
    }
    __syncthreads();
    int k2 = blockIdx.y * 32 + threadIdx.x;
    #pragma unroll
    for (int i = 0; i < 4; i++) {
        int n2 = blockIdx.x * 32 + threadIdx.y + i * 8;
        th[(size_t)n2 * Hh + k2] = __float2half(t[threadIdx.x][threadIdx.y + i * 8]);
    }
}

// generic: W [L][K][N] -> g_wth + l*LSTRIDE + dstOff as [N][K] fp16
__global__ void wsplit_kernel(const float* __restrict__ W, long dstOff, int K, int N) {
    __shared__ float t[32][33];
    int l = blockIdx.z;
    const float* Ws = W + (size_t)l * K * N;
    __half* th = g_wth + (size_t)l * LSTRIDE + dstOff;
    int n = blockIdx.x * 32 + threadIdx.x;
    #pragma unroll
    for (int i = 0; i < 4; i++) {
        int k = blockIdx.y * 32 + threadIdx.y + i * 8;
        t[threadIdx.y + i * 8][threadIdx.x] = Ws[(size_t)k * N + n];
    }
    __syncthreads();
    int k2 = blockIdx.y * 32 + threadIdx.x;
    #pragma unroll
    for (int i = 0; i < 4; i++) {
        int n2 = blockIdx.x * 32 + threadIdx.y + i * 8;
        th[(size_t)n2 * K + k2] = __float2half(t[threadIdx.x][threadIdx.y + i * 8]);
    }
}

__global__ void pack_bias_kernel(const float* __restrict__ bq, const float* __restrict__ bk,
                                 const float* __restrict__ bv) {
    int l = blockIdx.x, j = threadIdx.x;
    g_bqkv[l * QKVN + j]          = bq[l * Hh + j];
    g_bqkv[l * QKVN + Hh + j]     = bk[l * Hh + j];
    g_bqkv[l * QKVN + 2 * Hh + j] = bv[l * Hh + j];
}

// ---------------- embeddings + LN + mask bias ----------------
__global__ void embed_ln_kernel(const int* __restrict__ ids, const int* __restrict__ tys,
                                const float* __restrict__ word, const float* __restrict__ pos,
                                const float* __restrict__ typ,
                                const float* __restrict__ eg, const float* __restrict__ eb) {
    __shared__ float sred[9];
    int t = blockIdx.x;
    int s = t & (Ss - 1);
    int id = ids[t], ty = tys[t];
    float v[3];
    float loc = 0.f;
    #pragma unroll
    for (int i = 0; i < 3; i++) {
        int j = threadIdx.x + i * 256;
        v[i] = word[(size_t)id * Hh + j] + pos[(size_t)s * Hh + j] + typ[(size_t)ty * Hh + j];
        loc += v[i];
    }
    float mu = blk_sum256(loc, sred) * (1.0f / Hh);
    float l2 = 0.f;
    #pragma unroll
    for (int i = 0; i < 3; i++) { float d = v[i] - mu; l2 += d * d; }
    float var = blk_sum256(l2, sred) * (1.0f / Hh);
    float rstd = rsqrtf(var + EPS_LN);
    #pragma unroll
    for (int i = 0; i < 3; i++) {
        int j = threadIdx.x + i * 256;
        size_t idx = (size_t)t * Hh + j;
        float o = (v[i] - mu) * rstd * eg[j] + eb[j];
        g_x[idx] = o;
        split_store_h(o, &g_xhi[idx], &g_xlo[idx]);
    }
    if (threadIdx.x == 0) g_mbias[t] = (id > 0) ? 0.f : -10000.0f;
}

// ---------------- residual add + LN (in place on x), fused fp16 split ----------------
__global__ void add_ln_kernel(float* __restrict__ x, const float* __restrict__ y,
                              const float* __restrict__ g, const float* __restrict__ b) {
    __shared__ float sred[9];
    size_t base = (size_t)blockIdx.x * Hh;
    float v[3];
    float loc = 0.f;
    #pragma unroll
    for (int i = 0; i < 3; i++) {
        int j = threadIdx.x + i * 256;
        v[i] = x[base + j] + y[base + j];
        loc += v[i];
    }
    float mu = blk_sum256(loc, sred) * (1.0f / Hh);
    float l2 = 0.f;
    #pragma unroll
    for (int i = 0; i < 3; i++) { float d = v[i] - mu; l2 += d * d; }
    float var = blk_sum256(l2, sred) * (1.0f / Hh);
    float rstd = rsqrtf(var + EPS_LN);
    #pragma unroll
    for (int i = 0; i < 3; i++) {
        int j = threadIdx.x + i * 256;
        float o = (v[i] - mu) * rstd * g[j] + b[j];
        x[base + j] = o;
        split_store_h(o, &g_xhi[base + j], &g_xlo[base + j]);
    }
}

// ---------------- HMMA 2-term fp16 GEMM: C[4096, N] = (Ah+Al) @ Bh^T + bias ----------------
// A: hi/lo fp16 [M][K] (activations, exact to 2^-22); B: fp16 [N][K] (weights).
// CTA 128x128, K-chunk 32, double-buffered cp.async, 8 warps (warp tile 64x32), 2 CTAs/SM.
#define GT_TILE  (128 * 80)        // bytes per sub-tile (32 fp16 cols padded to 80B rows)
#define GT_STAGE (3 * GT_TILE)     // Ah | Al | Bh = 30720
#define GSMEM    (2 * GT_STAGE)    // 61440
template <int OUTMODE>
__global__ void __launch_bounds__(256, 2) gemm_mma(
    const __half* __restrict__ Ahi, const __half* __restrict__ Alo,
    const __half* __restrict__ Bh,
    const float* __restrict__ bias,
    float* __restrict__ Cf, __half* __restrict__ Chi, __half* __restrict__ Clo,
    int K, int ldc)
{
    extern __shared__ char sm[];
    const uint32_t sb = smem_u32(sm);
    int tid = threadIdx.x, lane = tid & 31, wid = tid >> 5;
    int wm = wid >> 2, wn = wid & 3;              // warp tile rows wm*64, cols wn*32
    int m0 = blockIdx.y * 128, n0 = blockIdx.x * 128;

    // ldmatrix lane offsets
    int q = lane >> 3, r = lane & 7;
    uint32_t aLane = (uint32_t)(((q & 1) * 8 + r) * 80 + (q >> 1) * 16);
    uint32_t bLane = (uint32_t)(((q >> 1) * 8 + r) * 80 + (q & 1) * 16);

    float acc[4][4][4];
    #pragma unroll
    for (int mi = 0; mi < 4; mi++)
        #pragma unroll
        for (int ni = 0; ni < 4; ni++)
            #pragma unroll
            for (int e = 0; e < 4; e++) acc[mi][ni][e] = 0.f;

    int nchunk = K >> 5;

    // loader: 1536 x 16B per stage; 6 per thread
    auto load_stage = [&](int c) {
        int k0 = c << 5;
        uint32_t base = sb + (uint32_t)(c & 1) * GT_STAGE;
        #pragma unroll
        for (int i = 0; i < 6; i++) {
            int lin = tid + i * 256;              // 0..1535
            int tile = lin >> 9;                  // 0=Ah 1=Al 2=Bh
            int within = lin & 511;
            int row = within >> 2, seg = within & 3;
            uint32_t dst = base + (uint32_t)tile * GT_TILE + (uint32_t)(row * 80 + seg * 16);
            const __half* src;
            if (tile == 0)      src = Ahi + (size_t)(m0 + row) * K + k0 + seg * 8;
            else if (tile == 1) src = Alo + (size_t)(m0 + row) * K + k0 + seg * 8;
            else                src = Bh  + (size_t)(n0 + row) * K + k0 + seg * 8;
            cp_async16(dst, src);
        }
    };

    load_stage(0);
    CP_COMMIT();

    for (int c = 0; c < nchunk; c++) {
        if (c + 1 < nchunk) { load_stage(c + 1); CP_COMMIT(); CP_WAIT(1); }
        else { CP_WAIT(0); }
        __syncthreads();

        uint32_t base = sb + (uint32_t)(c & 1) * GT_STAGE;
        uint32_t aBaseH = base + (uint32_t)((wm * 64) * 80) + aLane;
        uint32_t aBaseL = aBaseH + GT_TILE;
        uint32_t bBase  = base + 2 * GT_TILE + (uint32_t)((wn * 32) * 80) + bLane;

        #pragma unroll
        for (int ks = 0; ks < 2; ks++) {
            uint32_t ko = (uint32_t)(ks * 32);
            uint32_t ah[4][4], al[4][4], bf[2][4];
            #pragma unroll
            for (int mi = 0; mi < 4; mi++)
                ldsm4(ah[mi][0], ah[mi][1], ah[mi][2], ah[mi][3],
                      aBaseH + (uint32_t)(mi * 16 * 80) + ko);
            #pragma unroll
            for (int mi = 0; mi < 4; mi++)
                ldsm4(al[mi][0], al[mi][1], al[mi][2], al[mi][3],
                      aBaseL + (uint32_t)(mi * 16 * 80) + ko);
            #pragma unroll
            for (int p = 0; p < 2; p++)
                ldsm4(bf[p][0], bf[p][1], bf[p][2], bf[p][3],
                      bBase + (uint32_t)(p * 16 * 80) + ko);
            #pragma unroll
            for (int mi = 0; mi < 4; mi++)
                #pragma unroll
                for (int ni = 0; ni < 4; ni++) {
                    int p = ni >> 1, su = ni & 1;
                    mma16816(acc[mi][ni], ah[mi][0], ah[mi][1], ah[mi][2], ah[mi][3],
                             bf[p][su * 2], bf[p][su * 2 + 1]);
                }
            #pragma unroll
            for (int mi = 0; mi < 4; mi++)
                #pragma unroll
                for (int ni = 0; ni < 4; ni++) {
                    int p = ni >> 1, su = ni & 1;
                    mma16816(acc[mi][ni], al[mi][0], al[mi][1], al[mi][2], al[mi][3],
                             bf[p][su * 2], bf[p][su * 2 + 1]);
                }
        }
        __syncthreads();
    }

    // ---------------- epilogue ----------------
    int rbase = m0 + wm * 64 + (lane >> 2);
    int cbase = n0 + wn * 32 + (lane & 3) * 2;
    #pragma unroll
    for (int mi = 0; mi < 4; mi++) {
        #pragma unroll
        for (int ni = 0; ni < 4; ni++) {
            int row = rbase + mi * 16;
            int col = cbase + ni * 8;
            float b0 = bias[col], b1 = bias[col + 1];
            float v0 = acc[mi][ni][0] + b0, v1 = acc[mi][ni][1] + b1;
            float v2 = acc[mi][ni][2] + b0, v3 = acc[mi][ni][3] + b1;
            if (OUTMODE == 0) {
                *(float2*)(Cf + (size_t)row * ldc + col)       = make_float2(v0, v1);
                *(float2*)(Cf + (size_t)(row + 8) * ldc + col) = make_float2(v2, v3);
            } else {
                v0 = gelu_tanh(v0); v1 = gelu_tanh(v1);
                v2 = gelu_tanh(v2); v3 = gelu_tanh(v3);
                __half h0 = __float2half(v0), h1 = __float2half(v1);
                __half h2 = __float2half(v2), h3 = __float2half(v3);
                *(unsigned*)(Chi + (size_t)row * ldc + col) =
                    (unsigned)__half_as_ushort(h0) | ((unsigned)__half_as_ushort(h1) << 16);
                *(unsigned*)(Clo + (size_t)row * ldc + col) =
                    pack2h(v0 - __half2float(h0), v1 - __half2float(h1));
                *(unsigned*)(Chi + (size_t)(row + 8) * ldc + col) =
                    (unsigned)__half_as_ushort(h2) | ((unsigned)__half_as_ushort(h3) << 16);
                *(unsigned*)(Clo + (size_t)(row + 8) * ldc + col) =
                    pack2h(v2 - __half2float(h2), v3 - __half2float(h3));
            }
        }
    }
}

// ---------------- attention: one-pass, scores cached in smem ----------------
#define ATTN_SMEM ((2*Ss*DHh + Ss*129 + Ss) * (int)sizeof(float))
__global__ void __launch_bounds__(128) attn_kernel(const float* __restrict__ Qkv,
                                                   const float* __restrict__ bias,
                                                   __half* __restrict__ chi,
                                                   __half* __restrict__ clo) {
    extern __shared__ float smf[];
    float* Ks = smf;
    float* Vs = smf + Ss * DHh;
    float* S  = smf + 2 * Ss * DHh;
    float* biasS = S + Ss * 129;
    int bn = blockIdx.x;
    int b = bn / NHh, n = bn % NHh;
    int tid = threadIdx.x;
    const float scale = 0.125f;

    #pragma unroll
    for (int i = 0; i < 16; i++) {
        int linr = tid + i * 128;
        int j = linr >> 4, c4 = (linr & 15) * 4;
        size_t rowb = (size_t)(b * Ss + j) * QKVN + n * DHh + c4;
        *(float4*)&Ks[j * DHh + c4] = *(const float4*)(Qkv + rowb + Hh);
        *(float4*)&Vs[j * DHh + c4] = *(const float4*)(Qkv + rowb + 2 * Hh);
    }
    biasS[tid] = bias[b * Ss + tid];
    __syncthreads();

    int qi = tid;
    float Qr[DHh];
    const float4* qp = (const float4*)(Qkv + (size_t)(b * Ss + qi) * QKVN + n * DHh);
    #pragma unroll
    for (int i = 0; i < 16; i++) {
        float4 v4 = qp[i];
        Qr[i * 4 + 0] = v4.x; Qr[i * 4 + 1] = v4.y; Qr[i * 4 + 2] = v4.z; Qr[i * 4 + 3] = v4.w;
    }

    float* Srow = S + qi * 129;
    float m = -1e30f;
    #pragma unroll 1
    for (int j = 0; j < Ss; j += 4) {
        const float* k0 = Ks + j * DHh;
        float s0 = 0.f, s1 = 0.f, s2 = 0.f, s3 = 0.f;
        #pragma unroll
        for (int d = 0; d < DHh; d++) {
            float qd = Qr[d];
            s0 = fmaf(qd, k0[d], s0);
            s1 = fmaf(qd, k0[DHh + d], s1);
            s2 = fmaf(qd, k0[2 * DHh + d], s2);
            s3 = fmaf(qd, k0[3 * DHh + d], s3);
        }
        s0 = fmaf(s0, scale, biasS[j]);
        s1 = fmaf(s1, scale, biasS[j + 1]);
        s2 = fmaf(s2, scale, biasS[j + 2]);
        s3 = fmaf(s3, scale, biasS[j + 3]);
        Srow[j] = s0; Srow[j + 1] = s1; Srow[j + 2] = s2; Srow[j + 3] = s3;
        m = fmaxf(m, fmaxf(fmaxf(s0, s1), fmaxf(s2, s3)));
    }
    float lsum = 0.f;
    #pragma unroll 4
    for (int j = 0; j < Ss; j++) {
        float p = __expf(Srow[j] - m);
        Srow[j] = p;
        lsum += p;
    }
    float inv_l = 1.0f / lsum;

    float acc[DHh];
    #pragma unroll
    for (int d = 0; d < DHh; d++) acc[d] = 0.f;
    #pragma unroll 1
    for (int j = 0; j < Ss; j++) {
        float p = Srow[j];
        const float* vr = Vs + j * DHh;
        #pragma unroll
        for (int d = 0; d < DHh; d++) acc[d] = fmaf(p, vr[d], acc[d]);
    }
    size_t obase = (size_t)(b * Ss + qi) * Hh + n * DHh;
    #pragma unroll
    for (int d = 0; d < DHh; d += 2) {
        float v0 = acc[d] * inv_l, v1 = acc[d + 1] * inv_l;
        __half h0 = __float2half(v0), h1 = __float2half(v1);
        *(unsigned*)(chi + obase + d) =
            (unsigned)__half_as_ushort(h0) | ((unsigned)__half_as_ushort(h1) << 16);
        *(unsigned*)(clo + obase + d) =
            pack2h(v0 - __half2float(h0), v1 - __half2float(h1));
    }
}

// ---------------- CLS extraction + norm ----------------
__global__ void cls_kernel() {
    __shared__ float sred[9];
    int b = blockIdx.x;
    float loc = 0.f;
    #pragma unroll
    for (int i = 0; i < 3; i++) {
        int j = threadIdx.x + i * 256;
        float v = g_x[(size_t)(b * Ss) * Hh + j];
        g_cls[b * Hh + j] = v;
        loc += v * v;
    }
    float s = blk_sum256(loc, sred);
    if (threadIdx.x == 0) g_cn[b] = fmaxf(sqrtf(s), EPS_COS);
}

__global__ void reset_best_kernel() {
    if (threadIdx.x < Bb) g_best[threadIdx.x] = 0ull;
}

// ---------------- cosine + per-block argmax reduction ----------------
__global__ void __launch_bounds__(128) cos_kernel(const float* __restrict__ lab,
                                                  float* __restrict__ out) {
    __shared__ float clsS[Bb][33];
    __shared__ float sInvCn[Bb];
    int l = blockIdx.x * 128 + threadIdx.x;
    bool valid = (l < NLl);
    if (threadIdx.x < Bb) sInvCn[threadIdx.x] = 1.0f / g_cn[threadIdx.x];

    float acc[Bb];
    #pragma unroll
    for (int bb = 0; bb < Bb; bb++) acc[bb] = 0.f;

    for (int k0 = 0; k0 < Hh; k0 += 32) {
        #pragma unroll
        for (int i = 0; i < 8; i++) {
            int idx = threadIdx.x + i * 128;
            int bb = idx >> 5, kk = idx & 31;
            clsS[bb][kk] = g_cls[bb * Hh + k0 + kk];
        }
        __syncthreads();
        if (valid) {
            float lv[32];
            const float4* lp = (const float4*)(lab + (size_t)l * Hh + k0);
            #pragma unroll
            for (int i = 0; i < 8; i++) {
                float4 v4 = lp[i];
                lv[i * 4] = v4.x; lv[i * 4 + 1] = v4.y; lv[i * 4 + 2] = v4.z; lv[i * 4 + 3] = v4.w;
            }
            #pragma unroll
            for (int bb = 0; bb < Bb; bb++) {
                float a = acc[bb];
                #pragma unroll
                for (int kk = 0; kk < 32; kk++) a = fmaf(clsS[bb][kk], lv[kk], a);
                acc[bb] = a;
            }
        }
        __syncthreads();
    }

    float invl = 0.f;
    if (valid) {
        float s = 0.f;
        const float4* lp = (const float4*)(lab + (size_t)l * Hh);
        #pragma unroll 4
        for (int i = 0; i < Hh / 4; i++) {
            float4 v4 = lp[i];
            s += v4.x * v4.x + v4.y * v4.y + v4.z * v4.z + v4.w * v4.w;
        }
        invl = 1.0f / fmaxf(sqrtf(s), EPS_COS);
    }

    int lane = threadIdx.x & 31;
    #pragma unroll 1
    for (int bb = 0; bb < Bb; bb++) {
        unsigned long long key = 0ull;
        if (valid) {
            float c = acc[bb] * invl * sInvCn[bb];
            out[(size_t)bb * NLl + l] = c;
            key = pack_key(c, l);
        }
        #pragma unroll
        for (int o = 16; o > 0; o >>= 1) {
            unsigned long long other = __shfl_down_sync(0xffffffffu, key, o);
            key = (other > key) ? other : key;
        }
        if (lane == 0) atomicMax(&g_best[bb], key);
    }
}

__global__ void ids_out_kernel(float* __restrict__ out) {
    int b = threadIdx.x;
    if (b < Bb) {
        unsigned idpart = (unsigned)(g_best[b] & 0xFFFFFFFFull);
        out[(size_t)Bb * NLl + b] = (float)(0xFFFFFFFFu - idpart);
    }
}

// ---------------- host orchestration ----------------
extern "C" void kernel_launch(void* const* d_in, const int* in_sizes, int n_in,
                              void* d_out, int out_size) {
    const int*   ids  = (const int*)d_in[0];
    const int*   tys  = (const int*)d_in[1];
    const float* word = (const float*)d_in[2];
    const float* pos  = (const float*)d_in[3];
    const float* typ  = (const float*)d_in[4];
    const float* eg   = (const float*)d_in[5];
    const float* eb   = (const float*)d_in[6];
    const float* Wq   = (const float*)d_in[7];
    const float* bq   = (const float*)d_in[8];
    const float* Wk   = (const float*)d_in[9];
    const float* bk   = (const float*)d_in[10];
    const float* Wv   = (const float*)d_in[11];
    const float* bv   = (const float*)d_in[12];
    const float* Wo   = (const float*)d_in[13];
    const float* bo   = (const float*)d_in[14];
    const float* g1   = (const float*)d_in[15];
    const float* be1  = (const float*)d_in[16];
    const float* W1   = (const float*)d_in[17];
    const float* b1   = (const float*)d_in[18];
    const float* W2   = (const float*)d_in[19];
    const float* b2   = (const float*)d_in[20];
    const float* g2   = (const float*)d_in[21];
    const float* be2  = (const float*)d_in[22];
    const float* lab  = (const float*)d_in[23];
    float* out = (float*)d_out;

    float *px, *py, *pqkv, *pmbias, *pbqkv;
    __half *pxhi, *pxlo, *pchi, *pclo, *phhi, *phlo, *pwth;
    cudaGetSymbolAddress((void**)&px,    g_x);
    cudaGetSymbolAddress((void**)&py,    g_y);
    cudaGetSymbolAddress((void**)&pqkv,  g_qkv);
    cudaGetSymbolAddress((void**)&pmbias,g_mbias);
    cudaGetSymbolAddress((void**)&pbqkv, g_bqkv);
    cudaGetSymbolAddress((void**)&pxhi,  g_xhi);
    cudaGetSymbolAddress((void**)&pxlo,  g_xlo);
    cudaGetSymbolAddress((void**)&pchi,  g_chi);
    cudaGetSymbolAddress((void**)&pclo,  g_clo);
    cudaGetSymbolAddress((void**)&phhi,  g_hhi);
    cudaGetSymbolAddress((void**)&phlo,  g_hlo);
    cudaGetSymbolAddress((void**)&pwth,  g_wth);

    cudaFuncSetAttribute(attn_kernel, cudaFuncAttributeMaxDynamicSharedMemorySize, ATTN_SMEM);
    cudaFuncSetAttribute(gemm_mma<0>, cudaFuncAttributeMaxDynamicSharedMemorySize, GSMEM);
    cudaFuncSetAttribute(gemm_mma<1>, cudaFuncAttributeMaxDynamicSharedMemorySize, GSMEM);

    // launch order arranged so ncu (-s 5 -c 1) captures the first QKV GEMM (launch #6)
    dim3 tb(32, 8);
    wsplit4_kernel<<<dim3(24, 24, 48), tb>>>(Wq, Wk, Wv, Wo);                 // 1
    wsplit_kernel<<<dim3(FFf / 32, Hh / 32, Ll), tb>>>(W1, OFF_W1, Hh, FFf);  // 2
    wsplit_kernel<<<dim3(Hh / 32, FFf / 32, Ll), tb>>>(W2, OFF_W2, FFf, Hh);  // 3
    pack_bias_kernel<<<Ll, Hh>>>(bq, bk, bv);                                 // 4
    embed_ln_kernel<<<NTOK, 256>>>(ids, tys, word, pos, typ, eg, eb);         // 5

    for (int l = 0; l < Ll; l++) {
        size_t wl = (size_t)l * LSTRIDE;
        gemm_mma<0><<<dim3(QKVN / 128, 32), 256, GSMEM>>>(                    // 6 = captured
            pxhi, pxlo, pwth + wl, pbqkv + l * QKVN,
            pqkv, nullptr, nullptr, Hh, QKVN);
        attn_kernel<<<Bb * NHh, 128, ATTN_SMEM>>>(pqkv, pmbias, pchi, pclo);
        gemm_mma<0><<<dim3(Hh / 128, 32), 256, GSMEM>>>(
            pchi, pclo, pwth + wl + OFF_O, bo + (size_t)l * Hh,
            py, nullptr, nullptr, Hh, Hh);
        add_ln_kernel<<<NTOK, 256>>>(px, py, g1 + (size_t)l * Hh, be1 + (size_t)l * Hh);
        gemm_mma<1><<<dim3(FFf / 128, 32), 256, GSMEM>>>(
            pxhi, pxlo, pwth + wl + OFF_W1, b1 + (size_t)l * FFf,
            nullptr, phhi, phlo, Hh, FFf);
        gemm_mma<0><<<dim3(Hh / 128, 32), 256, GSMEM>>>(
            phhi, phlo, pwth + wl + OFF_W2, b2 + (size_t)l * Hh,
            py, nullptr, nullptr, FFf, Hh);
        add_ln_kernel<<<NTOK, 256>>>(px, py, g2 + (size_t)l * Hh, be2 + (size_t)l * Hh);
    }

    cls_kernel<<<Bb, 256>>>();
    reset_best_kernel<<<1, 32>>>();
    cos_kernel<<<(NLl + 127) / 128, 128>>>(lab, out);
    if (out_size >= Bb * NLl + Bb) ids_out_kernel<<<1, 32>>>(out);
}